// round 1
// baseline (speedup 1.0000x reference)
#include <cuda_runtime.h>
#include <math.h>
#include <stdint.h>

#define BB   8
#define LL   1024
#define SS   77
#define DD   512
#define HH   8
#define DHD  64
#define CDIM 768
#define FFD  2048
#define ROWS  (BB*LL)   /* 8192 */
#define CROWS (BB*SS)   /* 616  */
#define TQ   4

// Scratch layout (floats):
//  h   @ 0         (8192*512)
//  q   @ 4194304
//  k   @ 8388608
//  v   @ 12582912
//  o   @ 16777216
//  x1  @ 20971520
//  p   @ 25165824  (8192*4096)
//  act @ 58720256  (8192*2048)
__device__ float g_scratch[75497472];

// ---------------------------------------------------------------------------
// LayerNorm: one block (128 threads) per row of 512
// ---------------------------------------------------------------------------
__global__ void ln_kernel(const float* __restrict__ x, const float* __restrict__ gamma,
                          const float* __restrict__ beta, float* __restrict__ out)
{
    int row = blockIdx.x;
    const float* xr = x + (long)row * DD;
    float* orw = out + (long)row * DD;
    int t = threadIdx.x;

    float v[4];
    float s = 0.f;
#pragma unroll
    for (int i = 0; i < 4; i++) { v[i] = xr[t + i*128]; s += v[i]; }

    __shared__ float red[4];
    __shared__ float red2[4];
#pragma unroll
    for (int off = 16; off; off >>= 1) s += __shfl_xor_sync(0xffffffffu, s, off);
    if ((t & 31) == 0) red[t >> 5] = s;
    __syncthreads();
    float mean = (red[0] + red[1] + red[2] + red[3]) * (1.f/512.f);

    float sq = 0.f;
#pragma unroll
    for (int i = 0; i < 4; i++) { float d = v[i] - mean; sq += d*d; }
#pragma unroll
    for (int off = 16; off; off >>= 1) sq += __shfl_xor_sync(0xffffffffu, sq, off);
    if ((t & 31) == 0) red2[t >> 5] = sq;
    __syncthreads();
    float var = (red2[0] + red2[1] + red2[2] + red2[3]) * (1.f/512.f);
    float rstd = rsqrtf(var + 1e-5f);

#pragma unroll
    for (int i = 0; i < 4; i++) {
        int c = t + i*128;
        orw[c] = (v[i] - mean) * rstd * gamma[c] + beta[c];
    }
}

// ---------------------------------------------------------------------------
// Generic SGEMM: C[M,N] = A[M,K] @ B[K,N] (+bias[N]) (+res[M,N])
// 64x64 tile, BK=16, 256 threads, 4x4 per thread. N multiple of 64, K mult of 16.
// ---------------------------------------------------------------------------
__global__ void gemm_kernel(const float* __restrict__ A, const float* __restrict__ Bm,
                            const float* __restrict__ bias, const float* __restrict__ res,
                            float* __restrict__ C, int M, int N, int K)
{
    __shared__ float As[16][68];   // [k][m], padded to reduce store conflicts, keeps 16B align
    __shared__ float Bs[16][64];   // [k][n]

    int tid = threadIdx.x;
    int tx = tid & 15;        // 0..15 -> n quad
    int ty = tid >> 4;        // 0..15 -> m quad
    int m0 = blockIdx.y * 64;
    int n0 = blockIdx.x * 64;

    int aCol = tid & 15;      // k within tile
    int aRow = tid >> 4;      // m base, step 16
    int bCol = tid & 63;      // n
    int bRow = tid >> 6;      // k base, step 4

    float acc[4][4] = {};

    for (int k0 = 0; k0 < K; k0 += 16) {
#pragma unroll
        for (int i = 0; i < 4; i++) {
            int m = m0 + aRow + i*16;
            As[aCol][aRow + i*16] = (m < M) ? A[(long)m * K + k0 + aCol] : 0.f;
        }
#pragma unroll
        for (int i = 0; i < 4; i++) {
            int kk = k0 + bRow + i*4;
            Bs[bRow + i*4][bCol] = Bm[(long)kk * N + n0 + bCol];
        }
        __syncthreads();

#pragma unroll
        for (int kk = 0; kk < 16; kk++) {
            float4 a = *(const float4*)&As[kk][ty*4];
            float4 b = *(const float4*)&Bs[kk][tx*4];
            acc[0][0] += a.x*b.x; acc[0][1] += a.x*b.y; acc[0][2] += a.x*b.z; acc[0][3] += a.x*b.w;
            acc[1][0] += a.y*b.x; acc[1][1] += a.y*b.y; acc[1][2] += a.y*b.z; acc[1][3] += a.y*b.w;
            acc[2][0] += a.z*b.x; acc[2][1] += a.z*b.y; acc[2][2] += a.z*b.z; acc[2][3] += a.z*b.w;
            acc[3][0] += a.w*b.x; acc[3][1] += a.w*b.y; acc[3][2] += a.w*b.z; acc[3][3] += a.w*b.w;
        }
        __syncthreads();
    }

#pragma unroll
    for (int i = 0; i < 4; i++) {
        int m = m0 + ty*4 + i;
        if (m >= M) continue;
#pragma unroll
        for (int j = 0; j < 4; j++) {
            int n = n0 + tx*4 + j;
            float cv = acc[i][j];
            if (bias) cv += bias[n];
            long idx = (long)m * N + n;
            if (res) cv += res[idx];
            C[idx] = cv;
        }
    }
}

// ---------------------------------------------------------------------------
// Attention: block = 128 threads, TQ=4 query rows for one (b,h).
// Full scores in smem, softmax normalized in place, then V pass.
// Q rows: b*LL + q ; K/V rows: b*kvL + k ; head h at col h*64.
// ---------------------------------------------------------------------------
__global__ void attn_kernel(const float* __restrict__ Q, const float* __restrict__ K,
                            const float* __restrict__ V, float* __restrict__ O,
                            int Lk, int kvL, float scale)
{
    int b = blockIdx.z, h = blockIdx.y, q0 = blockIdx.x * TQ;
    int tid = threadIdx.x;

    __shared__ float qs[TQ][DHD];
    __shared__ float Ks[64][DHD + 1];
    __shared__ float sc[TQ][LL];

    // load q (pre-scaled)
    for (int i = tid; i < TQ*DHD; i += 128) {
        int qq = i >> 6, d = i & 63;
        qs[qq][d] = Q[((long)(b*LL + q0 + qq)) * DD + h*DHD + d] * scale;
    }
    __syncthreads();

    int LkPad = ((Lk + 63) >> 6) << 6;

    // ---- score pass ----
    for (int kt = 0; kt < Lk; kt += 64) {
        for (int i = tid; i < 64*DHD; i += 128) {
            int kk = i >> 6, d = i & 63;
            int krow = kt + kk;
            Ks[kk][d] = (krow < Lk) ? K[((long)(b*kvL + krow)) * DD + h*DHD + d] : 0.f;
        }
        __syncthreads();
#pragma unroll
        for (int r = 0; r < 2; r++) {
            int idx = tid + r*128;           // 0..255
            int qq = idx >> 6, kk = idx & 63;
            float s = 0.f;
#pragma unroll
            for (int d = 0; d < DHD; d++) s += qs[qq][d] * Ks[kk][d];
            sc[qq][kt + kk] = (kt + kk < Lk) ? s : -1e30f;
        }
        __syncthreads();
    }

    // ---- softmax: warp w owns row w ----
    int w = tid >> 5, lane = tid & 31;
    {
        float m = -1e30f;
        for (int k = lane; k < LkPad; k += 32) m = fmaxf(m, sc[w][k]);
#pragma unroll
        for (int off = 16; off; off >>= 1) m = fmaxf(m, __shfl_xor_sync(0xffffffffu, m, off));
        float s = 0.f;
        for (int k = lane; k < LkPad; k += 32) {
            float e = __expf(sc[w][k] - m);
            sc[w][k] = e;
            s += e;
        }
#pragma unroll
        for (int off = 16; off; off >>= 1) s += __shfl_xor_sync(0xffffffffu, s, off);
        float inv = 1.f / s;
        for (int k = lane; k < LkPad; k += 32) sc[w][k] *= inv;
    }
    __syncthreads();

    // ---- V pass: thread owns d = tid%64, q rows {tid/64, tid/64 + 2} ----
    int d = tid & 63, qh = tid >> 6;
    float acc0 = 0.f, acc1 = 0.f;
    for (int kt = 0; kt < Lk; kt += 64) {
        for (int i = tid; i < 64*DHD; i += 128) {
            int kk = i >> 6, dd = i & 63;
            int krow = kt + kk;
            Ks[kk][dd] = (krow < Lk) ? V[((long)(b*kvL + krow)) * DD + h*DHD + dd] : 0.f;
        }
        __syncthreads();
#pragma unroll 8
        for (int kk = 0; kk < 64; kk++) {
            float vv = Ks[kk][d];
            acc0 += sc[qh    ][kt + kk] * vv;
            acc1 += sc[qh + 2][kt + kk] * vv;
        }
        __syncthreads();
    }
    O[((long)(b*LL + q0 + qh    )) * DD + h*DHD + d] = acc0;
    O[((long)(b*LL + q0 + qh + 2)) * DD + h*DHD + d] = acc1;
}

// ---------------------------------------------------------------------------
// GEGLU: act[r,c] = p[r,c] * gelu_exact(p[r, FF + c])
// ---------------------------------------------------------------------------
__global__ void geglu_kernel(const float* __restrict__ p, float* __restrict__ act)
{
    long i = (long)blockIdx.x * blockDim.x + threadIdx.x;
    long row = i / FFD, col = i - row * FFD;
    float val  = p[row * (2*FFD) + col];
    float gate = p[row * (2*FFD) + FFD + col];
    act[i] = val * gate * normcdff(gate);
}

// ---------------------------------------------------------------------------
extern "C" void kernel_launch(void* const* d_in, const int* in_sizes, int n_in,
                              void* d_out, int out_size)
{
    const float* x    = (const float*)d_in[0];
    const float* ctx  = (const float*)d_in[1];
    const float* ln1g = (const float*)d_in[2];
    const float* ln1b = (const float*)d_in[3];
    const float* ln2g = (const float*)d_in[4];
    const float* ln2b = (const float*)d_in[5];
    const float* ln3g = (const float*)d_in[6];
    const float* ln3b = (const float*)d_in[7];
    const float* a1wq = (const float*)d_in[8];
    const float* a1wk = (const float*)d_in[9];
    const float* a1wv = (const float*)d_in[10];
    const float* a1wo = (const float*)d_in[11];
    const float* a1bo = (const float*)d_in[12];
    const float* a2wq = (const float*)d_in[13];
    const float* a2wk = (const float*)d_in[14];
    const float* a2wv = (const float*)d_in[15];
    const float* a2wo = (const float*)d_in[16];
    const float* a2bo = (const float*)d_in[17];
    const float* ffw1 = (const float*)d_in[18];
    const float* ffb1 = (const float*)d_in[19];
    const float* ffw2 = (const float*)d_in[20];
    const float* ffb2 = (const float*)d_in[21];
    float* out = (float*)d_out;

    float* base = nullptr;
    cudaGetSymbolAddress((void**)&base, g_scratch);
    float* h   = base;
    float* q   = base + 4194304;
    float* k   = base + 8388608;
    float* v   = base + 12582912;
    float* o   = base + 16777216;
    float* x1  = base + 20971520;
    float* p   = base + 25165824;
    float* act = base + 58720256;

    const float scale = 0.125f;  // DH^-0.5
    dim3 g512(512/64, ROWS/64);
    dim3 gctx(512/64, (CROWS + 63)/64);
    dim3 gff1(4096/64, ROWS/64);
    dim3 gattn(LL/TQ, HH, BB);

    // --- self attention block ---
    ln_kernel<<<ROWS, 128>>>(x, ln1g, ln1b, h);
    gemm_kernel<<<g512, 256>>>(h, a1wq, nullptr, nullptr, q, ROWS, 512, 512);
    gemm_kernel<<<g512, 256>>>(h, a1wk, nullptr, nullptr, k, ROWS, 512, 512);
    gemm_kernel<<<g512, 256>>>(h, a1wv, nullptr, nullptr, v, ROWS, 512, 512);
    attn_kernel<<<gattn, 128>>>(q, k, v, o, LL, LL, scale);
    gemm_kernel<<<g512, 256>>>(o, a1wo, a1bo, x, x1, ROWS, 512, 512);

    // --- cross attention block ---
    ln_kernel<<<ROWS, 128>>>(x1, ln2g, ln2b, h);
    gemm_kernel<<<g512, 256>>>(h, a2wq, nullptr, nullptr, q, ROWS, 512, 512);
    gemm_kernel<<<gctx, 256>>>(ctx, a2wk, nullptr, nullptr, k, CROWS, 512, CDIM);
    gemm_kernel<<<gctx, 256>>>(ctx, a2wv, nullptr, nullptr, v, CROWS, 512, CDIM);
    attn_kernel<<<gattn, 128>>>(q, k, v, o, SS, SS, scale);
    gemm_kernel<<<g512, 256>>>(o, a2wo, a2bo, x1, x1, ROWS, 512, 512);

    // --- GEGLU feed-forward ---
    ln_kernel<<<ROWS, 128>>>(x1, ln3g, ln3b, h);
    gemm_kernel<<<gff1, 256>>>(h, ffw1, ffb1, nullptr, p, ROWS, 4096, 512);
    geglu_kernel<<<(ROWS * FFD) / 256, 256>>>(p, act);
    gemm_kernel<<<g512, 256>>>(act, ffw2, ffb2, x1, out, ROWS, 512, FFD);
}

// round 2
// speedup vs baseline: 1.2336x; 1.2336x over previous
#include <cuda_runtime.h>
#include <cuda_bf16.h>
#include <math.h>
#include <stdint.h>

typedef __nv_bfloat16 bf16;

#define BB   8
#define LL   1024
#define SS   77
#define DD   512
#define HH   8
#define DHD  64
#define CDIM 768
#define FFD  2048
#define ROWS  (BB*LL)   /* 8192 */
#define CROWS (BB*SS)   /* 616  */
#define TQ   4

#define MB (1024u*1024u)
__device__ __align__(256) unsigned char g_scratch[448u*MB];

// ---------------------------------------------------------------------------
// LayerNorm (unchanged)
// ---------------------------------------------------------------------------
__global__ void ln_kernel(const float* __restrict__ x, const float* __restrict__ gamma,
                          const float* __restrict__ beta, float* __restrict__ out)
{
    int row = blockIdx.x;
    const float* xr = x + (long)row * DD;
    float* orw = out + (long)row * DD;
    int t = threadIdx.x;

    float v[4];
    float s = 0.f;
#pragma unroll
    for (int i = 0; i < 4; i++) { v[i] = xr[t + i*128]; s += v[i]; }

    __shared__ float red[4];
    __shared__ float red2[4];
#pragma unroll
    for (int off = 16; off; off >>= 1) s += __shfl_xor_sync(0xffffffffu, s, off);
    if ((t & 31) == 0) red[t >> 5] = s;
    __syncthreads();
    float mean = (red[0] + red[1] + red[2] + red[3]) * (1.f/512.f);

    float sq = 0.f;
#pragma unroll
    for (int i = 0; i < 4; i++) { float d = v[i] - mean; sq += d*d; }
#pragma unroll
    for (int off = 16; off; off >>= 1) sq += __shfl_xor_sync(0xffffffffu, sq, off);
    if ((t & 31) == 0) red2[t >> 5] = sq;
    __syncthreads();
    float var = (red2[0] + red2[1] + red2[2] + red2[3]) * (1.f/512.f);
    float rstd = rsqrtf(var + 1e-5f);

#pragma unroll
    for (int i = 0; i < 4; i++) {
        int c = t + i*128;
        orw[c] = (v[i] - mean) * rstd * gamma[c] + beta[c];
    }
}

// ---------------------------------------------------------------------------
// fp32 -> (bf16 hi, bf16 lo) elementwise split
// ---------------------------------------------------------------------------
__global__ void split_kernel(const float* __restrict__ in, bf16* __restrict__ hi,
                             bf16* __restrict__ lo, int n)
{
    int i = blockIdx.x * blockDim.x + threadIdx.x;
    if (i >= n) return;
    float x = in[i];
    bf16 h = __float2bfloat16(x);
    hi[i] = h;
    lo[i] = __float2bfloat16(x - __bfloat162float(h));
}

// ---------------------------------------------------------------------------
// W[K,N] fp32 -> WT_hi[N,K], WT_lo[N,K] bf16 (tiled transpose + split)
// K,N multiples of 32.
// ---------------------------------------------------------------------------
__global__ void tsplit_kernel(const float* __restrict__ W, bf16* __restrict__ Th,
                              bf16* __restrict__ Tl, int K, int N)
{
    __shared__ float t[32][33];
    int k0 = blockIdx.y * 32, n0 = blockIdx.x * 32;
    int x = threadIdx.x, y = threadIdx.y; // 32 x 8
#pragma unroll
    for (int i = 0; i < 32; i += 8)
        t[y + i][x] = W[(size_t)(k0 + y + i) * N + n0 + x];
    __syncthreads();
#pragma unroll
    for (int i = 0; i < 32; i += 8) {
        float v = t[x][y + i];                 // = W[k0+x][n0+y+i]
        bf16 h = __float2bfloat16(v);
        bf16 l = __float2bfloat16(v - __bfloat162float(h));
        size_t o = (size_t)(n0 + y + i) * K + k0 + x;
        Th[o] = h; Tl[o] = l;
    }
}

// ---------------------------------------------------------------------------
// bf16-split tensor-core GEMM:
//   C[M,N] = A[M,K] @ B^T  where Bh/Bl are [N,K] (pre-transposed)
//   C = Ah*Bh + Ah*Bl + Al*Bh  (fp32 accumulate)  (+bias) (+res)
// Block 128x128x32, 256 threads (8 warps, 2x4), warp tile 64x32,
// 3-stage cp.async pipeline. N % 128 == 0, K % 32 == 0; M guarded.
// ---------------------------------------------------------------------------
#define BM 128
#define BN 128
#define BKC 32
#define LDA 40                       /* smem row stride (bf16) */
#define ST_ELE (4*128*LDA)           /* bf16 per stage: Ah,Al,Bh,Bl */
#define S_AH 0
#define S_AL (128*LDA)
#define S_BH (2*128*LDA)
#define S_BL (3*128*LDA)
#define NSTAGE 3

extern __shared__ __align__(16) unsigned char dynsmem[];

__device__ __forceinline__ void cp16(uint32_t dst, const void* src, int srcsize) {
    asm volatile("cp.async.cg.shared.global [%0], [%1], 16, %2;\n"
                 :: "r"(dst), "l"(src), "r"(srcsize));
}
__device__ __forceinline__ void cp_commit() {
    asm volatile("cp.async.commit_group;\n" ::: "memory");
}
__device__ __forceinline__ void cp_wait2() {
    asm volatile("cp.async.wait_group 2;\n" ::: "memory");
}

#define MMA_BF16(d, a, b)                                                        \
    asm volatile("mma.sync.aligned.m16n8k16.row.col.f32.bf16.bf16.f32 "          \
                 "{%0,%1,%2,%3},{%4,%5,%6,%7},{%8,%9},{%0,%1,%2,%3};"            \
                 : "+f"(d[0]), "+f"(d[1]), "+f"(d[2]), "+f"(d[3])                 \
                 : "r"(a[0]), "r"(a[1]), "r"(a[2]), "r"(a[3]),                    \
                   "r"(b[0]), "r"(b[1]))

__global__ void __launch_bounds__(256)
gemm_mma(const bf16* __restrict__ Ah, const bf16* __restrict__ Al,
         const bf16* __restrict__ Bh, const bf16* __restrict__ Bl,
         const float* __restrict__ bias, const float* __restrict__ res,
         float* __restrict__ C, int M, int N, int K)
{
    bf16* sm = (bf16*)dynsmem;
    uint32_t smb = (uint32_t)__cvta_generic_to_shared(sm);

    int tid = threadIdx.x;
    int m0 = blockIdx.y * BM, n0 = blockIdx.x * BN;
    int wid = tid >> 5, lane = tid & 31;
    int wm = (wid & 1) * 64, wn = (wid >> 1) * 32;
    int g = lane >> 2, tq = lane & 3;

    float c[4][4][4];
#pragma unroll
    for (int i = 0; i < 4; i++)
#pragma unroll
        for (int j = 0; j < 4; j++)
#pragma unroll
            for (int r = 0; r < 4; r++) c[i][j][r] = 0.f;

    // staging mapping: each thread covers rows r0, r0+64 at k-chunk kc (8 bf16)
    int r0 = tid >> 2, kc = tid & 3;
    int mA0 = m0 + r0, mA1 = m0 + r0 + 64;
    int szA0 = (mA0 < M) ? 16 : 0;
    int szA1 = (mA1 < M) ? 16 : 0;
    const bf16* pAh0 = Ah + (size_t)min(mA0, M-1) * K + kc*8;
    const bf16* pAh1 = Ah + (size_t)min(mA1, M-1) * K + kc*8;
    const bf16* pAl0 = Al + (size_t)min(mA0, M-1) * K + kc*8;
    const bf16* pAl1 = Al + (size_t)min(mA1, M-1) * K + kc*8;
    const bf16* pBh0 = Bh + (size_t)(n0 + r0) * K + kc*8;
    const bf16* pBh1 = Bh + (size_t)(n0 + r0 + 64) * K + kc*8;
    const bf16* pBl0 = Bl + (size_t)(n0 + r0) * K + kc*8;
    const bf16* pBl1 = Bl + (size_t)(n0 + r0 + 64) * K + kc*8;
    uint32_t dA0 = smb + (uint32_t)(S_AH + r0*LDA + kc*8) * 2;
    uint32_t dA1 = smb + (uint32_t)(S_AH + (r0+64)*LDA + kc*8) * 2;
    uint32_t dL0 = smb + (uint32_t)(S_AL + r0*LDA + kc*8) * 2;
    uint32_t dL1 = smb + (uint32_t)(S_AL + (r0+64)*LDA + kc*8) * 2;
    uint32_t dB0 = smb + (uint32_t)(S_BH + r0*LDA + kc*8) * 2;
    uint32_t dB1 = smb + (uint32_t)(S_BH + (r0+64)*LDA + kc*8) * 2;
    uint32_t dC0 = smb + (uint32_t)(S_BL + r0*LDA + kc*8) * 2;
    uint32_t dC1 = smb + (uint32_t)(S_BL + (r0+64)*LDA + kc*8) * 2;

#define LOAD_STAGE(s, k0v)                                                     \
    do {                                                                       \
        uint32_t so = (uint32_t)(s) * (ST_ELE * 2);                            \
        cp16(dA0 + so, pAh0 + (k0v), szA0);                                    \
        cp16(dA1 + so, pAh1 + (k0v), szA1);                                    \
        cp16(dL0 + so, pAl0 + (k0v), szA0);                                    \
        cp16(dL1 + so, pAl1 + (k0v), szA1);                                    \
        cp16(dB0 + so, pBh0 + (k0v), 16);                                      \
        cp16(dB1 + so, pBh1 + (k0v), 16);                                      \
        cp16(dC0 + so, pBl0 + (k0v), 16);                                      \
        cp16(dC1 + so, pBl1 + (k0v), 16);                                      \
        cp_commit();                                                           \
    } while (0)

    int nk = K / BKC;
    LOAD_STAGE(0, 0);
    LOAD_STAGE(1, BKC);
    LOAD_STAGE(2, 2*BKC);

    for (int kt = 0; kt < nk; kt++) {
        cp_wait2();
        __syncthreads();
        bf16* st = sm + (kt % 3) * ST_ELE;

#pragma unroll
        for (int kk = 0; kk < BKC; kk += 16) {
            uint32_t ah[4][4], al[4][4], bh[4][2], bl[4][2];
#pragma unroll
            for (int mb = 0; mb < 4; mb++) {
                int rA = wm + mb*16 + g;
                const bf16* ph = st + S_AH + rA*LDA + kk + tq*2;
                const bf16* pl = st + S_AL + rA*LDA + kk + tq*2;
                ah[mb][0] = *(const uint32_t*)(ph);
                ah[mb][1] = *(const uint32_t*)(ph + 8*LDA);
                ah[mb][2] = *(const uint32_t*)(ph + 8);
                ah[mb][3] = *(const uint32_t*)(ph + 8*LDA + 8);
                al[mb][0] = *(const uint32_t*)(pl);
                al[mb][1] = *(const uint32_t*)(pl + 8*LDA);
                al[mb][2] = *(const uint32_t*)(pl + 8);
                al[mb][3] = *(const uint32_t*)(pl + 8*LDA + 8);
            }
#pragma unroll
            for (int nb = 0; nb < 4; nb++) {
                int rB = wn + nb*8 + g;
                const bf16* ph = st + S_BH + rB*LDA + kk + tq*2;
                const bf16* pl = st + S_BL + rB*LDA + kk + tq*2;
                bh[nb][0] = *(const uint32_t*)(ph);
                bh[nb][1] = *(const uint32_t*)(ph + 8);
                bl[nb][0] = *(const uint32_t*)(pl);
                bl[nb][1] = *(const uint32_t*)(pl + 8);
            }
#pragma unroll
            for (int mb = 0; mb < 4; mb++)
#pragma unroll
                for (int nb = 0; nb < 4; nb++) {
                    MMA_BF16(c[mb][nb], ah[mb], bh[nb]);
                    MMA_BF16(c[mb][nb], ah[mb], bl[nb]);
                    MMA_BF16(c[mb][nb], al[mb], bh[nb]);
                }
        }
        __syncthreads();
        if (kt + 3 < nk) LOAD_STAGE((kt + 3) % 3, (kt + 3) * BKC);
    }

    // epilogue
#pragma unroll
    for (int mb = 0; mb < 4; mb++) {
#pragma unroll
        for (int nb = 0; nb < 4; nb++) {
            int m = m0 + wm + mb*16 + g;
            int n = n0 + wn + nb*8 + tq*2;
            float b0 = bias ? bias[n]   : 0.f;
            float b1 = bias ? bias[n+1] : 0.f;
            if (m < M) {
                size_t idx = (size_t)m * N + n;
                float v0 = c[mb][nb][0] + b0;
                float v1 = c[mb][nb][1] + b1;
                if (res) { v0 += res[idx]; v1 += res[idx+1]; }
                C[idx] = v0; C[idx+1] = v1;
            }
            if (m + 8 < M) {
                size_t idx = (size_t)(m+8) * N + n;
                float v0 = c[mb][nb][2] + b0;
                float v1 = c[mb][nb][3] + b1;
                if (res) { v0 += res[idx]; v1 += res[idx+1]; }
                C[idx] = v0; C[idx+1] = v1;
            }
        }
    }
#undef LOAD_STAGE
}

// ---------------------------------------------------------------------------
// Attention (unchanged from round 1)
// ---------------------------------------------------------------------------
__global__ void attn_kernel(const float* __restrict__ Q, const float* __restrict__ K,
                            const float* __restrict__ V, float* __restrict__ O,
                            int Lk, int kvL, float scale)
{
    int b = blockIdx.z, h = blockIdx.y, q0 = blockIdx.x * TQ;
    int tid = threadIdx.x;

    __shared__ float qs[TQ][DHD];
    __shared__ float Ks[64][DHD + 1];
    __shared__ float sc[TQ][LL];

    for (int i = tid; i < TQ*DHD; i += 128) {
        int qq = i >> 6, d = i & 63;
        qs[qq][d] = Q[((long)(b*LL + q0 + qq)) * DD + h*DHD + d] * scale;
    }
    __syncthreads();

    int LkPad = ((Lk + 63) >> 6) << 6;

    for (int kt = 0; kt < Lk; kt += 64) {
        for (int i = tid; i < 64*DHD; i += 128) {
            int kk = i >> 6, d = i & 63;
            int krow = kt + kk;
            Ks[kk][d] = (krow < Lk) ? K[((long)(b*kvL + krow)) * DD + h*DHD + d] : 0.f;
        }
        __syncthreads();
#pragma unroll
        for (int r = 0; r < 2; r++) {
            int idx = tid + r*128;
            int qq = idx >> 6, kk = idx & 63;
            float s = 0.f;
#pragma unroll
            for (int d = 0; d < DHD; d++) s += qs[qq][d] * Ks[kk][d];
            sc[qq][kt + kk] = (kt + kk < Lk) ? s : -1e30f;
        }
        __syncthreads();
    }

    int w = tid >> 5, lane = tid & 31;
    {
        float m = -1e30f;
        for (int k = lane; k < LkPad; k += 32) m = fmaxf(m, sc[w][k]);
#pragma unroll
        for (int off = 16; off; off >>= 1) m = fmaxf(m, __shfl_xor_sync(0xffffffffu, m, off));
        float s = 0.f;
        for (int k = lane; k < LkPad; k += 32) {
            float e = __expf(sc[w][k] - m);
            sc[w][k] = e;
            s += e;
        }
#pragma unroll
        for (int off = 16; off; off >>= 1) s += __shfl_xor_sync(0xffffffffu, s, off);
        float inv = 1.f / s;
        for (int k = lane; k < LkPad; k += 32) sc[w][k] *= inv;
    }
    __syncthreads();

    int d = tid & 63, qh = tid >> 6;
    float acc0 = 0.f, acc1 = 0.f;
    for (int kt = 0; kt < Lk; kt += 64) {
        for (int i = tid; i < 64*DHD; i += 128) {
            int kk = i >> 6, dd = i & 63;
            int krow = kt + kk;
            Ks[kk][dd] = (krow < Lk) ? V[((long)(b*kvL + krow)) * DD + h*DHD + dd] : 0.f;
        }
        __syncthreads();
#pragma unroll 8
        for (int kk = 0; kk < 64; kk++) {
            float vv = Ks[kk][d];
            acc0 += sc[qh    ][kt + kk] * vv;
            acc1 += sc[qh + 2][kt + kk] * vv;
        }
        __syncthreads();
    }
    O[((long)(b*LL + q0 + qh    )) * DD + h*DHD + d] = acc0;
    O[((long)(b*LL + q0 + qh + 2)) * DD + h*DHD + d] = acc1;
}

// ---------------------------------------------------------------------------
// GEGLU
// ---------------------------------------------------------------------------
__global__ void geglu_kernel(const float* __restrict__ p, float* __restrict__ act)
{
    long i = (long)blockIdx.x * blockDim.x + threadIdx.x;
    long row = i / FFD, col = i - row * FFD;
    float val  = p[row * (2*FFD) + col];
    float gate = p[row * (2*FFD) + FFD + col];
    act[i] = val * gate * normcdff(gate);
}

// ---------------------------------------------------------------------------
extern "C" void kernel_launch(void* const* d_in, const int* in_sizes, int n_in,
                              void* d_out, int out_size)
{
    const float* x    = (const float*)d_in[0];
    const float* ctx  = (const float*)d_in[1];
    const float* ln1g = (const float*)d_in[2];
    const float* ln1b = (const float*)d_in[3];
    const float* ln2g = (const float*)d_in[4];
    const float* ln2b = (const float*)d_in[5];
    const float* ln3g = (const float*)d_in[6];
    const float* ln3b = (const float*)d_in[7];
    const float* a1wq = (const float*)d_in[8];
    const float* a1wk = (const float*)d_in[9];
    const float* a1wv = (const float*)d_in[10];
    const float* a1wo = (const float*)d_in[11];
    const float* a1bo = (const float*)d_in[12];
    const float* a2wq = (const float*)d_in[13];
    const float* a2wk = (const float*)d_in[14];
    const float* a2wv = (const float*)d_in[15];
    const float* a2wo = (const float*)d_in[16];
    const float* a2bo = (const float*)d_in[17];
    const float* ffw1 = (const float*)d_in[18];
    const float* ffb1 = (const float*)d_in[19];
    const float* ffw2 = (const float*)d_in[20];
    const float* ffb2 = (const float*)d_in[21];
    float* out = (float*)d_out;

    unsigned char* base = nullptr;
    cudaGetSymbolAddress((void**)&base, g_scratch);

    float* h   = (float*)(base + 0u*MB);
    float* q   = (float*)(base + 16u*MB);
    float* k   = (float*)(base + 32u*MB);
    float* v   = (float*)(base + 48u*MB);
    float* o   = (float*)(base + 64u*MB);
    float* x1  = (float*)(base + 80u*MB);
    float* p   = (float*)(base + 96u*MB);
    float* act = (float*)(base + 224u*MB);
    bf16* hs_h = (bf16*)(base + 288u*MB);
    bf16* hs_l = (bf16*)(base + 296u*MB);
    bf16* os_h = (bf16*)(base + 304u*MB);
    bf16* os_l = (bf16*)(base + 312u*MB);
    bf16* cx_h = (bf16*)(base + 320u*MB);
    bf16* cx_l = (bf16*)(base + 321u*MB);
    bf16* as_h = (bf16*)(base + 322u*MB);
    bf16* as_l = (bf16*)(base + 354u*MB);
    bf16* wcur = (bf16*)(base + 386u*MB);

    // weight transposed-split buffers
    bf16 *w1q_h, *w1q_l, *w1k_h, *w1k_l, *w1v_h, *w1v_l, *w1o_h, *w1o_l;
    bf16 *w2q_h, *w2q_l, *w2k_h, *w2k_l, *w2v_h, *w2v_l, *w2o_h, *w2o_l;
    bf16 *f1_h, *f1_l, *f2_h, *f2_l;
    {
        size_t cur = 0;
        auto al2 = [&](size_t n, bf16** hh, bf16** ll) {
            *hh = wcur + cur; cur += n; *ll = wcur + cur; cur += n;
        };
        al2(512*512,  &w1q_h, &w1q_l);
        al2(512*512,  &w1k_h, &w1k_l);
        al2(512*512,  &w1v_h, &w1v_l);
        al2(512*512,  &w1o_h, &w1o_l);
        al2(512*512,  &w2q_h, &w2q_l);
        al2(768*512,  &w2k_h, &w2k_l);
        al2(768*512,  &w2v_h, &w2v_l);
        al2(512*512,  &w2o_h, &w2o_l);
        al2(512*4096, &f1_h,  &f1_l);
        al2(2048*512, &f2_h,  &f2_l);
    }

    const int GEMM_SMEM = NSTAGE * ST_ELE * 2;  // bytes
    static bool attr_set = false;
    if (!attr_set) {
        cudaFuncSetAttribute(gemm_mma, cudaFuncAttributeMaxDynamicSharedMemorySize, GEMM_SMEM);
        attr_set = true;
    }

    dim3 tb(32, 8);
    // weight conversions
    tsplit_kernel<<<dim3(512/32, 512/32), tb>>>(a1wq, w1q_h, w1q_l, 512, 512);
    tsplit_kernel<<<dim3(512/32, 512/32), tb>>>(a1wk, w1k_h, w1k_l, 512, 512);
    tsplit_kernel<<<dim3(512/32, 512/32), tb>>>(a1wv, w1v_h, w1v_l, 512, 512);
    tsplit_kernel<<<dim3(512/32, 512/32), tb>>>(a1wo, w1o_h, w1o_l, 512, 512);
    tsplit_kernel<<<dim3(512/32, 512/32), tb>>>(a2wq, w2q_h, w2q_l, 512, 512);
    tsplit_kernel<<<dim3(512/32, 768/32), tb>>>(a2wk, w2k_h, w2k_l, 768, 512);
    tsplit_kernel<<<dim3(512/32, 768/32), tb>>>(a2wv, w2v_h, w2v_l, 768, 512);
    tsplit_kernel<<<dim3(512/32, 512/32), tb>>>(a2wo, w2o_h, w2o_l, 512, 512);
    tsplit_kernel<<<dim3(4096/32, 512/32), tb>>>(ffw1, f1_h, f1_l, 512, 4096);
    tsplit_kernel<<<dim3(512/32, 2048/32), tb>>>(ffw2, f2_h, f2_l, 2048, 512);
    // ctx split
    split_kernel<<<(CROWS*CDIM + 255)/256, 256>>>(ctx, cx_h, cx_l, CROWS*CDIM);

    const float scale = 0.125f;
    dim3 g512(512/128, ROWS/128);            // (4, 64)
    dim3 gctx(512/128, (CROWS + 127)/128);   // (4, 5)
    dim3 gff1(4096/128, ROWS/128);           // (32, 64)
    dim3 gattn(LL/TQ, HH, BB);

    // --- self attention block ---
    ln_kernel<<<ROWS, 128>>>(x, ln1g, ln1b, h);
    split_kernel<<<(ROWS*DD)/256, 256>>>(h, hs_h, hs_l, ROWS*DD);
    gemm_mma<<<g512, 256, GEMM_SMEM>>>(hs_h, hs_l, w1q_h, w1q_l, nullptr, nullptr, q, ROWS, 512, 512);
    gemm_mma<<<g512, 256, GEMM_SMEM>>>(hs_h, hs_l, w1k_h, w1k_l, nullptr, nullptr, k, ROWS, 512, 512);
    gemm_mma<<<g512, 256, GEMM_SMEM>>>(hs_h, hs_l, w1v_h, w1v_l, nullptr, nullptr, v, ROWS, 512, 512);
    attn_kernel<<<gattn, 128>>>(q, k, v, o, LL, LL, scale);
    split_kernel<<<(ROWS*DD)/256, 256>>>(o, os_h, os_l, ROWS*DD);
    gemm_mma<<<g512, 256, GEMM_SMEM>>>(os_h, os_l, w1o_h, w1o_l, a1bo, x, x1, ROWS, 512, 512);

    // --- cross attention block ---
    ln_kernel<<<ROWS, 128>>>(x1, ln2g, ln2b, h);
    split_kernel<<<(ROWS*DD)/256, 256>>>(h, hs_h, hs_l, ROWS*DD);
    gemm_mma<<<g512, 256, GEMM_SMEM>>>(hs_h, hs_l, w2q_h, w2q_l, nullptr, nullptr, q, ROWS, 512, 512);
    gemm_mma<<<gctx, 256, GEMM_SMEM>>>(cx_h, cx_l, w2k_h, w2k_l, nullptr, nullptr, k, CROWS, 512, CDIM);
    gemm_mma<<<gctx, 256, GEMM_SMEM>>>(cx_h, cx_l, w2v_h, w2v_l, nullptr, nullptr, v, CROWS, 512, CDIM);
    attn_kernel<<<gattn, 128>>>(q, k, v, o, SS, SS, scale);
    split_kernel<<<(ROWS*DD)/256, 256>>>(o, os_h, os_l, ROWS*DD);
    gemm_mma<<<g512, 256, GEMM_SMEM>>>(os_h, os_l, w2o_h, w2o_l, a2bo, x1, x1, ROWS, 512, 512);

    // --- GEGLU feed-forward ---
    ln_kernel<<<ROWS, 128>>>(x1, ln3g, ln3b, h);
    split_kernel<<<(ROWS*DD)/256, 256>>>(h, hs_h, hs_l, ROWS*DD);
    gemm_mma<<<gff1, 256, GEMM_SMEM>>>(hs_h, hs_l, f1_h, f1_l, ffb1, nullptr, p, ROWS, 4096, 512);
    geglu_kernel<<<(ROWS * FFD) / 256, 256>>>(p, act);
    split_kernel<<<(ROWS*FFD)/256, 256>>>(act, as_h, as_l, ROWS*FFD);
    gemm_mma<<<g512, 256, GEMM_SMEM>>>(as_h, as_l, f2_h, f2_l, ffb2, x1, out, ROWS, 512, FFD);
}

// round 3
// speedup vs baseline: 2.8268x; 2.2916x over previous
#include <cuda_runtime.h>
#include <cuda_bf16.h>
#include <math.h>
#include <stdint.h>

typedef __nv_bfloat16 bf16;

#define BB   8
#define LL   1024
#define SS   77
#define DD   512
#define HH   8
#define DHD  64
#define CDIM 768
#define FFD  2048
#define ROWS  (BB*LL)   /* 8192 */
#define CROWS (BB*SS)   /* 616  */

#define MB (1024u*1024u)
__device__ __align__(256) unsigned char g_scratch[448u*MB];

extern __shared__ __align__(16) unsigned char dynsmem[];

// ---------------------------------------------------------------------------
// helpers
// ---------------------------------------------------------------------------
__device__ __forceinline__ uint32_t pack2(bf16 a, bf16 b) {
    __nv_bfloat162 t(a, b);
    return *(uint32_t*)&t;
}
__device__ __forceinline__ void split2(float x, float y, uint32_t& h, uint32_t& l) {
    bf16 hx = __float2bfloat16(x), hy = __float2bfloat16(y);
    bf16 lx = __float2bfloat16(x - __bfloat162float(hx));
    bf16 ly = __float2bfloat16(y - __bfloat162float(hy));
    h = pack2(hx, hy);
    l = pack2(lx, ly);
}

// ---------------------------------------------------------------------------
// LayerNorm: fp32 in -> (hi, lo) bf16 out
// ---------------------------------------------------------------------------
__global__ void ln_kernel(const float* __restrict__ x, const float* __restrict__ gamma,
                          const float* __restrict__ beta,
                          bf16* __restrict__ oh, bf16* __restrict__ ol)
{
    int row = blockIdx.x;
    const float* xr = x + (long)row * DD;
    int t = threadIdx.x;

    float v[4];
    float s = 0.f;
#pragma unroll
    for (int i = 0; i < 4; i++) { v[i] = xr[t + i*128]; s += v[i]; }

    __shared__ float red[4];
    __shared__ float red2[4];
#pragma unroll
    for (int off = 16; off; off >>= 1) s += __shfl_xor_sync(0xffffffffu, s, off);
    if ((t & 31) == 0) red[t >> 5] = s;
    __syncthreads();
    float mean = (red[0] + red[1] + red[2] + red[3]) * (1.f/512.f);

    float sq = 0.f;
#pragma unroll
    for (int i = 0; i < 4; i++) { float d = v[i] - mean; sq += d*d; }
#pragma unroll
    for (int off = 16; off; off >>= 1) sq += __shfl_xor_sync(0xffffffffu, sq, off);
    if ((t & 31) == 0) red2[t >> 5] = sq;
    __syncthreads();
    float var = (red2[0] + red2[1] + red2[2] + red2[3]) * (1.f/512.f);
    float rstd = rsqrtf(var + 1e-5f);

#pragma unroll
    for (int i = 0; i < 4; i++) {
        int c = t + i*128;
        float y = (v[i] - mean) * rstd * gamma[c] + beta[c];
        bf16 h = __float2bfloat16(y);
        oh[(long)row * DD + c] = h;
        ol[(long)row * DD + c] = __float2bfloat16(y - __bfloat162float(h));
    }
}

// ---------------------------------------------------------------------------
// fp32 -> (bf16 hi, bf16 lo) elementwise split (used for ctx only)
// ---------------------------------------------------------------------------
__global__ void split_kernel(const float* __restrict__ in, bf16* __restrict__ hi,
                             bf16* __restrict__ lo, int n)
{
    int i = blockIdx.x * blockDim.x + threadIdx.x;
    if (i >= n) return;
    float x = in[i];
    bf16 h = __float2bfloat16(x);
    hi[i] = h;
    lo[i] = __float2bfloat16(x - __bfloat162float(h));
}

// ---------------------------------------------------------------------------
// W[K,N] fp32 -> WT_hi[N,K], WT_lo[N,K] bf16 (tiled transpose + split)
// ---------------------------------------------------------------------------
__global__ void tsplit_kernel(const float* __restrict__ W, bf16* __restrict__ Th,
                              bf16* __restrict__ Tl, int K, int N)
{
    __shared__ float t[32][33];
    int k0 = blockIdx.y * 32, n0 = blockIdx.x * 32;
    int x = threadIdx.x, y = threadIdx.y; // 32 x 8
#pragma unroll
    for (int i = 0; i < 32; i += 8)
        t[y + i][x] = W[(size_t)(k0 + y + i) * N + n0 + x];
    __syncthreads();
#pragma unroll
    for (int i = 0; i < 32; i += 8) {
        float v = t[x][y + i];
        bf16 h = __float2bfloat16(v);
        bf16 l = __float2bfloat16(v - __bfloat162float(h));
        size_t o = (size_t)(n0 + y + i) * K + k0 + x;
        Th[o] = h; Tl[o] = l;
    }
}

// ---------------------------------------------------------------------------
// bf16-split tensor-core GEMM (mainloop unchanged from round 2).
// Epilogue: if Ch != null -> write (hi,lo) of (acc+bias); else fp32 +bias +res.
// ---------------------------------------------------------------------------
#define BKC 32
#define LDA 40
#define ST_ELE (4*128*LDA)
#define S_AH 0
#define S_AL (128*LDA)
#define S_BH (2*128*LDA)
#define S_BL (3*128*LDA)
#define NSTAGE 3

__device__ __forceinline__ void cp16(uint32_t dst, const void* src, int srcsize) {
    asm volatile("cp.async.cg.shared.global [%0], [%1], 16, %2;\n"
                 :: "r"(dst), "l"(src), "r"(srcsize));
}
__device__ __forceinline__ void cp_commit() {
    asm volatile("cp.async.commit_group;\n" ::: "memory");
}
__device__ __forceinline__ void cp_wait2() {
    asm volatile("cp.async.wait_group 2;\n" ::: "memory");
}

#define MMA_BF16(d, a0, a1, a2, a3, b0, b1)                                      \
    asm volatile("mma.sync.aligned.m16n8k16.row.col.f32.bf16.bf16.f32 "          \
                 "{%0,%1,%2,%3},{%4,%5,%6,%7},{%8,%9},{%0,%1,%2,%3};"            \
                 : "+f"(d[0]), "+f"(d[1]), "+f"(d[2]), "+f"(d[3])                 \
                 : "r"(a0), "r"(a1), "r"(a2), "r"(a3), "r"(b0), "r"(b1))

__global__ void __launch_bounds__(256)
gemm_mma(const bf16* __restrict__ Ah, const bf16* __restrict__ Al,
         const bf16* __restrict__ Bh, const bf16* __restrict__ Bl,
         const float* __restrict__ bias, const float* __restrict__ res,
         float* __restrict__ C, bf16* __restrict__ Ch, bf16* __restrict__ Cl,
         int M, int N, int K)
{
    bf16* sm = (bf16*)dynsmem;
    uint32_t smb = (uint32_t)__cvta_generic_to_shared(sm);

    int tid = threadIdx.x;
    int m0 = blockIdx.y * 128, n0 = blockIdx.x * 128;
    int wid = tid >> 5, lane = tid & 31;
    int wm = (wid & 1) * 64, wn = (wid >> 1) * 32;
    int g = lane >> 2, tq = lane & 3;

    float c[4][4][4];
#pragma unroll
    for (int i = 0; i < 4; i++)
#pragma unroll
        for (int j = 0; j < 4; j++)
#pragma unroll
            for (int r = 0; r < 4; r++) c[i][j][r] = 0.f;

    int r0 = tid >> 2, kc = tid & 3;
    int mA0 = m0 + r0, mA1 = m0 + r0 + 64;
    int szA0 = (mA0 < M) ? 16 : 0;
    int szA1 = (mA1 < M) ? 16 : 0;
    const bf16* pAh0 = Ah + (size_t)min(mA0, M-1) * K + kc*8;
    const bf16* pAh1 = Ah + (size_t)min(mA1, M-1) * K + kc*8;
    const bf16* pAl0 = Al + (size_t)min(mA0, M-1) * K + kc*8;
    const bf16* pAl1 = Al + (size_t)min(mA1, M-1) * K + kc*8;
    const bf16* pBh0 = Bh + (size_t)(n0 + r0) * K + kc*8;
    const bf16* pBh1 = Bh + (size_t)(n0 + r0 + 64) * K + kc*8;
    const bf16* pBl0 = Bl + (size_t)(n0 + r0) * K + kc*8;
    const bf16* pBl1 = Bl + (size_t)(n0 + r0 + 64) * K + kc*8;
    uint32_t dA0 = smb + (uint32_t)(S_AH + r0*LDA + kc*8) * 2;
    uint32_t dA1 = smb + (uint32_t)(S_AH + (r0+64)*LDA + kc*8) * 2;
    uint32_t dL0 = smb + (uint32_t)(S_AL + r0*LDA + kc*8) * 2;
    uint32_t dL1 = smb + (uint32_t)(S_AL + (r0+64)*LDA + kc*8) * 2;
    uint32_t dB0 = smb + (uint32_t)(S_BH + r0*LDA + kc*8) * 2;
    uint32_t dB1 = smb + (uint32_t)(S_BH + (r0+64)*LDA + kc*8) * 2;
    uint32_t dC0 = smb + (uint32_t)(S_BL + r0*LDA + kc*8) * 2;
    uint32_t dC1 = smb + (uint32_t)(S_BL + (r0+64)*LDA + kc*8) * 2;

#define LOAD_STAGE(s, k0v)                                                     \
    do {                                                                       \
        uint32_t so = (uint32_t)(s) * (ST_ELE * 2);                            \
        cp16(dA0 + so, pAh0 + (k0v), szA0);                                    \
        cp16(dA1 + so, pAh1 + (k0v), szA1);                                    \
        cp16(dL0 + so, pAl0 + (k0v), szA0);                                    \
        cp16(dL1 + so, pAl1 + (k0v), szA1);                                    \
        cp16(dB0 + so, pBh0 + (k0v), 16);                                      \
        cp16(dB1 + so, pBh1 + (k0v), 16);                                      \
        cp16(dC0 + so, pBl0 + (k0v), 16);                                      \
        cp16(dC1 + so, pBl1 + (k0v), 16);                                      \
        cp_commit();                                                           \
    } while (0)

    int nk = K / BKC;
    LOAD_STAGE(0, 0);
    LOAD_STAGE(1, BKC);
    LOAD_STAGE(2, 2*BKC);

    for (int kt = 0; kt < nk; kt++) {
        cp_wait2();
        __syncthreads();
        bf16* st = sm + (kt % 3) * ST_ELE;

#pragma unroll
        for (int kk = 0; kk < BKC; kk += 16) {
            uint32_t ah[4][4], al[4][4], bh[4][2], bl[4][2];
#pragma unroll
            for (int mb = 0; mb < 4; mb++) {
                int rA = wm + mb*16 + g;
                const bf16* ph = st + S_AH + rA*LDA + kk + tq*2;
                const bf16* pl = st + S_AL + rA*LDA + kk + tq*2;
                ah[mb][0] = *(const uint32_t*)(ph);
                ah[mb][1] = *(const uint32_t*)(ph + 8*LDA);
                ah[mb][2] = *(const uint32_t*)(ph + 8);
                ah[mb][3] = *(const uint32_t*)(ph + 8*LDA + 8);
                al[mb][0] = *(const uint32_t*)(pl);
                al[mb][1] = *(const uint32_t*)(pl + 8*LDA);
                al[mb][2] = *(const uint32_t*)(pl + 8);
                al[mb][3] = *(const uint32_t*)(pl + 8*LDA + 8);
            }
#pragma unroll
            for (int nb = 0; nb < 4; nb++) {
                int rB = wn + nb*8 + g;
                const bf16* ph = st + S_BH + rB*LDA + kk + tq*2;
                const bf16* pl = st + S_BL + rB*LDA + kk + tq*2;
                bh[nb][0] = *(const uint32_t*)(ph);
                bh[nb][1] = *(const uint32_t*)(ph + 8);
                bl[nb][0] = *(const uint32_t*)(pl);
                bl[nb][1] = *(const uint32_t*)(pl + 8);
            }
#pragma unroll
            for (int mb = 0; mb < 4; mb++)
#pragma unroll
                for (int nb = 0; nb < 4; nb++) {
                    MMA_BF16(c[mb][nb], ah[mb][0], ah[mb][1], ah[mb][2], ah[mb][3], bh[nb][0], bh[nb][1]);
                    MMA_BF16(c[mb][nb], ah[mb][0], ah[mb][1], ah[mb][2], ah[mb][3], bl[nb][0], bl[nb][1]);
                    MMA_BF16(c[mb][nb], al[mb][0], al[mb][1], al[mb][2], al[mb][3], bh[nb][0], bh[nb][1]);
                }
        }
        __syncthreads();
        if (kt + 3 < nk) LOAD_STAGE((kt + 3) % 3, (kt + 3) * BKC);
    }

    // epilogue
#pragma unroll
    for (int mb = 0; mb < 4; mb++) {
#pragma unroll
        for (int nb = 0; nb < 4; nb++) {
            int m = m0 + wm + mb*16 + g;
            int n = n0 + wn + nb*8 + tq*2;
            float b0 = bias ? bias[n]   : 0.f;
            float b1 = bias ? bias[n+1] : 0.f;
            if (Ch) {
                if (m < M) {
                    size_t idx = (size_t)m * N + n;
                    uint32_t hh, ll;
                    split2(c[mb][nb][0] + b0, c[mb][nb][1] + b1, hh, ll);
                    *(uint32_t*)&Ch[idx] = hh;
                    *(uint32_t*)&Cl[idx] = ll;
                }
                if (m + 8 < M) {
                    size_t idx = (size_t)(m+8) * N + n;
                    uint32_t hh, ll;
                    split2(c[mb][nb][2] + b0, c[mb][nb][3] + b1, hh, ll);
                    *(uint32_t*)&Ch[idx] = hh;
                    *(uint32_t*)&Cl[idx] = ll;
                }
            } else {
                if (m < M) {
                    size_t idx = (size_t)m * N + n;
                    float v0 = c[mb][nb][0] + b0;
                    float v1 = c[mb][nb][1] + b1;
                    if (res) { v0 += res[idx]; v1 += res[idx+1]; }
                    C[idx] = v0; C[idx+1] = v1;
                }
                if (m + 8 < M) {
                    size_t idx = (size_t)(m+8) * N + n;
                    float v0 = c[mb][nb][2] + b0;
                    float v1 = c[mb][nb][3] + b1;
                    if (res) { v0 += res[idx]; v1 += res[idx+1]; }
                    C[idx] = v0; C[idx+1] = v1;
                }
            }
        }
    }
#undef LOAD_STAGE
}

// ---------------------------------------------------------------------------
// Flash-style attention, bf16-split MMA, online softmax.
// Block: 128 threads (4 warps); 64 query rows per block, 64-key tiles.
// Q/K/V inputs as (hi,lo) bf16 [rows, 512]; head h at col h*64.
// Output O written as (hi,lo) bf16.
// ---------------------------------------------------------------------------
#define ATT_LD 72
#define AQ_H 0
#define AQ_L (64*ATT_LD)
#define AK_H (2*64*ATT_LD)
#define AK_L (3*64*ATT_LD)
#define AV_H (4*64*ATT_LD)
#define AV_L (5*64*ATT_LD)
#define ATT_SMEM (6*64*ATT_LD*2)

__global__ void __launch_bounds__(128)
attn_mma(const bf16* __restrict__ Qh, const bf16* __restrict__ Ql,
         const bf16* __restrict__ Kh, const bf16* __restrict__ Kl,
         const bf16* __restrict__ Vh, const bf16* __restrict__ Vl,
         bf16* __restrict__ Oh, bf16* __restrict__ Ol,
         int Lk, int kvL)
{
    bf16* sm = (bf16*)dynsmem;
    int b = blockIdx.z, hh = blockIdx.y, q0 = blockIdx.x * 64;
    int tid = threadIdx.x;
    int wid = tid >> 5, lane = tid & 31;
    int g = lane >> 2, tq = lane & 3;
    int wm = wid * 16;

    // load Q tile (scaled by 0.125, exact for both hi and lo)
    for (int i = tid; i < 64*64; i += 128) {
        int qq = i >> 6, d = i & 63;
        size_t gidx = (size_t)(b*LL + q0 + qq) * DD + hh*DHD + d;
        sm[AQ_H + qq*ATT_LD + d] = __float2bfloat16(__bfloat162float(Qh[gidx]) * 0.125f);
        sm[AQ_L + qq*ATT_LD + d] = __float2bfloat16(__bfloat162float(Ql[gidx]) * 0.125f);
    }
    __syncthreads();

    // hoist Q A-fragments into registers
    uint32_t qa_h[4][4], qa_l[4][4];
#pragma unroll
    for (int ks = 0; ks < 4; ks++) {
        const bf16* ph = sm + AQ_H + (wm + g)*ATT_LD + ks*16 + tq*2;
        const bf16* pl = sm + AQ_L + (wm + g)*ATT_LD + ks*16 + tq*2;
        qa_h[ks][0] = *(const uint32_t*)(ph);
        qa_h[ks][1] = *(const uint32_t*)(ph + 8*ATT_LD);
        qa_h[ks][2] = *(const uint32_t*)(ph + 8);
        qa_h[ks][3] = *(const uint32_t*)(ph + 8*ATT_LD + 8);
        qa_l[ks][0] = *(const uint32_t*)(pl);
        qa_l[ks][1] = *(const uint32_t*)(pl + 8*ATT_LD);
        qa_l[ks][2] = *(const uint32_t*)(pl + 8);
        qa_l[ks][3] = *(const uint32_t*)(pl + 8*ATT_LD + 8);
    }

    float mr[2] = {-1e30f, -1e30f};
    float lr[2] = {0.f, 0.f};
    float co[8][4];
#pragma unroll
    for (int nb = 0; nb < 8; nb++)
#pragma unroll
        for (int r = 0; r < 4; r++) co[nb][r] = 0.f;

    for (int kt = 0; kt < Lk; kt += 64) {
        __syncthreads();
        // load K tile [key][d], V tile transposed [d][key]
        for (int i = tid; i < 64*64; i += 128) {
            int kk = i >> 6, d = i & 63;
            int krow = kt + kk;
            if (krow < Lk) {
                size_t gidx = (size_t)(b*kvL + krow) * DD + hh*DHD + d;
                sm[AK_H + kk*ATT_LD + d] = Kh[gidx];
                sm[AK_L + kk*ATT_LD + d] = Kl[gidx];
                sm[AV_H + d*ATT_LD + kk] = Vh[gidx];
                sm[AV_L + d*ATT_LD + kk] = Vl[gidx];
            } else {
                bf16 z = __float2bfloat16(0.f);
                sm[AK_H + kk*ATT_LD + d] = z;
                sm[AK_L + kk*ATT_LD + d] = z;
                sm[AV_H + d*ATT_LD + kk] = z;
                sm[AV_L + d*ATT_LD + kk] = z;
            }
        }
        __syncthreads();

        // S = Q K^T (split: 3 MMAs)
        float s[8][4];
#pragma unroll
        for (int nb = 0; nb < 8; nb++) {
#pragma unroll
            for (int r = 0; r < 4; r++) s[nb][r] = 0.f;
#pragma unroll
            for (int ks = 0; ks < 4; ks++) {
                const bf16* ph = sm + AK_H + (nb*8 + g)*ATT_LD + ks*16 + tq*2;
                const bf16* pl = sm + AK_L + (nb*8 + g)*ATT_LD + ks*16 + tq*2;
                uint32_t kb0 = *(const uint32_t*)(ph);
                uint32_t kb1 = *(const uint32_t*)(ph + 8);
                uint32_t kl0 = *(const uint32_t*)(pl);
                uint32_t kl1 = *(const uint32_t*)(pl + 8);
                MMA_BF16(s[nb], qa_h[ks][0], qa_h[ks][1], qa_h[ks][2], qa_h[ks][3], kb0, kb1);
                MMA_BF16(s[nb], qa_h[ks][0], qa_h[ks][1], qa_h[ks][2], qa_h[ks][3], kl0, kl1);
                MMA_BF16(s[nb], qa_l[ks][0], qa_l[ks][1], qa_l[ks][2], qa_l[ks][3], kb0, kb1);
            }
        }

        // mask out-of-range keys (cross-attention tail tile)
        if (kt + 64 > Lk) {
#pragma unroll
            for (int nb = 0; nb < 8; nb++) {
                int key = kt + nb*8 + tq*2;
                if (key     >= Lk) { s[nb][0] = -1e30f; s[nb][2] = -1e30f; }
                if (key + 1 >= Lk) { s[nb][1] = -1e30f; s[nb][3] = -1e30f; }
            }
        }

        // online softmax per row half (r=0: row g; r=1: row g+8)
#pragma unroll
        for (int r = 0; r < 2; r++) {
            int i0 = 2*r, i1 = 2*r + 1;
            float tm = -1e30f;
#pragma unroll
            for (int nb = 0; nb < 8; nb++)
                tm = fmaxf(tm, fmaxf(s[nb][i0], s[nb][i1]));
            tm = fmaxf(tm, __shfl_xor_sync(0xffffffffu, tm, 1));
            tm = fmaxf(tm, __shfl_xor_sync(0xffffffffu, tm, 2));
            float mnew = fmaxf(mr[r], tm);
            float alpha = __expf(mr[r] - mnew);
            mr[r] = mnew;
            float sum = 0.f;
#pragma unroll
            for (int nb = 0; nb < 8; nb++) {
                s[nb][i0] = __expf(s[nb][i0] - mnew); sum += s[nb][i0];
                s[nb][i1] = __expf(s[nb][i1] - mnew); sum += s[nb][i1];
            }
            sum += __shfl_xor_sync(0xffffffffu, sum, 1);
            sum += __shfl_xor_sync(0xffffffffu, sum, 2);
            lr[r] = lr[r] * alpha + sum;
#pragma unroll
            for (int nb = 0; nb < 8; nb++) { co[nb][i0] *= alpha; co[nb][i1] *= alpha; }
        }

        // O += P V (split: 3 MMAs); P fragments built from S fragments
#pragma unroll
        for (int ks = 0; ks < 4; ks++) {
            uint32_t a_h[4], a_l[4];
            split2(s[2*ks  ][0], s[2*ks  ][1], a_h[0], a_l[0]);
            split2(s[2*ks  ][2], s[2*ks  ][3], a_h[1], a_l[1]);
            split2(s[2*ks+1][0], s[2*ks+1][1], a_h[2], a_l[2]);
            split2(s[2*ks+1][2], s[2*ks+1][3], a_h[3], a_l[3]);
#pragma unroll
            for (int nb = 0; nb < 8; nb++) {
                const bf16* ph = sm + AV_H + (nb*8 + g)*ATT_LD + ks*16 + tq*2;
                const bf16* pl = sm + AV_L + (nb*8 + g)*ATT_LD + ks*16 + tq*2;
                uint32_t vb0 = *(const uint32_t*)(ph);
                uint32_t vb1 = *(const uint32_t*)(ph + 8);
                uint32_t vl0 = *(const uint32_t*)(pl);
                uint32_t vl1 = *(const uint32_t*)(pl + 8);
                MMA_BF16(co[nb], a_h[0], a_h[1], a_h[2], a_h[3], vb0, vb1);
                MMA_BF16(co[nb], a_h[0], a_h[1], a_h[2], a_h[3], vl0, vl1);
                MMA_BF16(co[nb], a_l[0], a_l[1], a_l[2], a_l[3], vb0, vb1);
            }
        }
    }

    // finalize: normalize and write (hi,lo)
    float inv0 = 1.f / lr[0], inv1 = 1.f / lr[1];
    int row0 = q0 + wm + g;
    size_t base0 = (size_t)(b*LL + row0) * DD + hh*DHD;
    size_t base1 = base0 + (size_t)8 * DD;
#pragma unroll
    for (int nb = 0; nb < 8; nb++) {
        int col = nb*8 + tq*2;
        uint32_t hh0, ll0, hh1, ll1;
        split2(co[nb][0]*inv0, co[nb][1]*inv0, hh0, ll0);
        split2(co[nb][2]*inv1, co[nb][3]*inv1, hh1, ll1);
        *(uint32_t*)&Oh[base0 + col] = hh0;
        *(uint32_t*)&Ol[base0 + col] = ll0;
        *(uint32_t*)&Oh[base1 + col] = hh1;
        *(uint32_t*)&Ol[base1 + col] = ll1;
    }
}

// ---------------------------------------------------------------------------
// GEGLU: (hi,lo) in -> (hi,lo) out
// ---------------------------------------------------------------------------
__global__ void geglu_kernel(const bf16* __restrict__ ph, const bf16* __restrict__ pl,
                             bf16* __restrict__ ah, bf16* __restrict__ al)
{
    long i = (long)blockIdx.x * blockDim.x + threadIdx.x;
    long row = i / FFD, col = i - row * FFD;
    long iv = row * (2*FFD) + col;
    long ig = iv + FFD;
    float val  = __bfloat162float(ph[iv]) + __bfloat162float(pl[iv]);
    float gate = __bfloat162float(ph[ig]) + __bfloat162float(pl[ig]);
    float r = val * gate * normcdff(gate);
    bf16 h = __float2bfloat16(r);
    ah[i] = h;
    al[i] = __float2bfloat16(r - __bfloat162float(h));
}

// ---------------------------------------------------------------------------
extern "C" void kernel_launch(void* const* d_in, const int* in_sizes, int n_in,
                              void* d_out, int out_size)
{
    const float* x    = (const float*)d_in[0];
    const float* ctx  = (const float*)d_in[1];
    const float* ln1g = (const float*)d_in[2];
    const float* ln1b = (const float*)d_in[3];
    const float* ln2g = (const float*)d_in[4];
    const float* ln2b = (const float*)d_in[5];
    const float* ln3g = (const float*)d_in[6];
    const float* ln3b = (const float*)d_in[7];
    const float* a1wq = (const float*)d_in[8];
    const float* a1wk = (const float*)d_in[9];
    const float* a1wv = (const float*)d_in[10];
    const float* a1wo = (const float*)d_in[11];
    const float* a1bo = (const float*)d_in[12];
    const float* a2wq = (const float*)d_in[13];
    const float* a2wk = (const float*)d_in[14];
    const float* a2wv = (const float*)d_in[15];
    const float* a2wo = (const float*)d_in[16];
    const float* a2bo = (const float*)d_in[17];
    const float* ffw1 = (const float*)d_in[18];
    const float* ffb1 = (const float*)d_in[19];
    const float* ffw2 = (const float*)d_in[20];
    const float* ffb2 = (const float*)d_in[21];
    float* out = (float*)d_out;

    unsigned char* base = nullptr;
    cudaGetSymbolAddress((void**)&base, g_scratch);

    bf16* h_h  = (bf16*)(base + 0u*MB);
    bf16* h_l  = (bf16*)(base + 8u*MB);
    bf16* q_h  = (bf16*)(base + 16u*MB);
    bf16* q_l  = (bf16*)(base + 24u*MB);
    bf16* k_h  = (bf16*)(base + 32u*MB);
    bf16* k_l  = (bf16*)(base + 40u*MB);
    bf16* v_h  = (bf16*)(base + 48u*MB);
    bf16* v_l  = (bf16*)(base + 56u*MB);
    bf16* o_h  = (bf16*)(base + 64u*MB);
    bf16* o_l  = (bf16*)(base + 72u*MB);
    float* x1  = (float*)(base + 80u*MB);
    bf16* p_h  = (bf16*)(base + 96u*MB);
    bf16* p_l  = (bf16*)(base + 160u*MB);
    bf16* a_h  = (bf16*)(base + 224u*MB);
    bf16* a_l  = (bf16*)(base + 256u*MB);
    bf16* cx_h = (bf16*)(base + 288u*MB);
    bf16* cx_l = (bf16*)(base + 290u*MB);
    bf16* wcur = (bf16*)(base + 292u*MB);

    bf16 *w1q_h, *w1q_l, *w1k_h, *w1k_l, *w1v_h, *w1v_l, *w1o_h, *w1o_l;
    bf16 *w2q_h, *w2q_l, *w2k_h, *w2k_l, *w2v_h, *w2v_l, *w2o_h, *w2o_l;
    bf16 *f1_h, *f1_l, *f2_h, *f2_l;
    {
        size_t cur = 0;
        auto al2 = [&](size_t n, bf16** hh, bf16** ll) {
            *hh = wcur + cur; cur += n; *ll = wcur + cur; cur += n;
        };
        al2(512*512,  &w1q_h, &w1q_l);
        al2(512*512,  &w1k_h, &w1k_l);
        al2(512*512,  &w1v_h, &w1v_l);
        al2(512*512,  &w1o_h, &w1o_l);
        al2(512*512,  &w2q_h, &w2q_l);
        al2(768*512,  &w2k_h, &w2k_l);
        al2(768*512,  &w2v_h, &w2v_l);
        al2(512*512,  &w2o_h, &w2o_l);
        al2(512*4096, &f1_h,  &f1_l);
        al2(2048*512, &f2_h,  &f2_l);
    }

    const int GEMM_SMEM = NSTAGE * ST_ELE * 2;
    static bool attr_set = false;
    if (!attr_set) {
        cudaFuncSetAttribute(gemm_mma, cudaFuncAttributeMaxDynamicSharedMemorySize, GEMM_SMEM);
        cudaFuncSetAttribute(attn_mma, cudaFuncAttributeMaxDynamicSharedMemorySize, ATT_SMEM);
        attr_set = true;
    }

    dim3 tb(32, 8);
    tsplit_kernel<<<dim3(512/32, 512/32), tb>>>(a1wq, w1q_h, w1q_l, 512, 512);
    tsplit_kernel<<<dim3(512/32, 512/32), tb>>>(a1wk, w1k_h, w1k_l, 512, 512);
    tsplit_kernel<<<dim3(512/32, 512/32), tb>>>(a1wv, w1v_h, w1v_l, 512, 512);
    tsplit_kernel<<<dim3(512/32, 512/32), tb>>>(a1wo, w1o_h, w1o_l, 512, 512);
    tsplit_kernel<<<dim3(512/32, 512/32), tb>>>(a2wq, w2q_h, w2q_l, 512, 512);
    tsplit_kernel<<<dim3(512/32, 768/32), tb>>>(a2wk, w2k_h, w2k_l, 768, 512);
    tsplit_kernel<<<dim3(512/32, 768/32), tb>>>(a2wv, w2v_h, w2v_l, 768, 512);
    tsplit_kernel<<<dim3(512/32, 512/32), tb>>>(a2wo, w2o_h, w2o_l, 512, 512);
    tsplit_kernel<<<dim3(4096/32, 512/32), tb>>>(ffw1, f1_h, f1_l, 512, 4096);
    tsplit_kernel<<<dim3(512/32, 2048/32), tb>>>(ffw2, f2_h, f2_l, 2048, 512);
    split_kernel<<<(CROWS*CDIM + 255)/256, 256>>>(ctx, cx_h, cx_l, CROWS*CDIM);

    dim3 g512(512/128, ROWS/128);
    dim3 gctx(512/128, (CROWS + 127)/128);
    dim3 gff1(4096/128, ROWS/128);
    dim3 gattn(LL/64, HH, BB);

    // --- self attention block ---
    ln_kernel<<<ROWS, 128>>>(x, ln1g, ln1b, h_h, h_l);
    gemm_mma<<<g512, 256, GEMM_SMEM>>>(h_h, h_l, w1q_h, w1q_l, nullptr, nullptr, nullptr, q_h, q_l, ROWS, 512, 512);
    gemm_mma<<<g512, 256, GEMM_SMEM>>>(h_h, h_l, w1k_h, w1k_l, nullptr, nullptr, nullptr, k_h, k_l, ROWS, 512, 512);
    gemm_mma<<<g512, 256, GEMM_SMEM>>>(h_h, h_l, w1v_h, w1v_l, nullptr, nullptr, nullptr, v_h, v_l, ROWS, 512, 512);
    attn_mma<<<gattn, 128, ATT_SMEM>>>(q_h, q_l, k_h, k_l, v_h, v_l, o_h, o_l, LL, LL);
    gemm_mma<<<g512, 256, GEMM_SMEM>>>(o_h, o_l, w1o_h, w1o_l, a1bo, x, x1, nullptr, nullptr, ROWS, 512, 512);

    // --- cross attention block ---
    ln_kernel<<<ROWS, 128>>>(x1, ln2g, ln2b, h_h, h_l);
    gemm_mma<<<g512, 256, GEMM_SMEM>>>(h_h, h_l, w2q_h, w2q_l, nullptr, nullptr, nullptr, q_h, q_l, ROWS, 512, 512);
    gemm_mma<<<gctx, 256, GEMM_SMEM>>>(cx_h, cx_l, w2k_h, w2k_l, nullptr, nullptr, nullptr, k_h, k_l, CROWS, 512, CDIM);
    gemm_mma<<<gctx, 256, GEMM_SMEM>>>(cx_h, cx_l, w2v_h, w2v_l, nullptr, nullptr, nullptr, v_h, v_l, CROWS, 512, CDIM);
    attn_mma<<<gattn, 128, ATT_SMEM>>>(q_h, q_l, k_h, k_l, v_h, v_l, o_h, o_l, SS, SS);
    gemm_mma<<<g512, 256, GEMM_SMEM>>>(o_h, o_l, w2o_h, w2o_l, a2bo, x1, x1, nullptr, nullptr, ROWS, 512, 512);

    // --- GEGLU feed-forward ---
    ln_kernel<<<ROWS, 128>>>(x1, ln3g, ln3b, h_h, h_l);
    gemm_mma<<<gff1, 256, GEMM_SMEM>>>(h_h, h_l, f1_h, f1_l, ffb1, nullptr, nullptr, p_h, p_l, ROWS, 4096, 512);
    geglu_kernel<<<(ROWS * FFD) / 256, 256>>>(p_h, p_l, a_h, a_l);
    gemm_mma<<<g512, 256, GEMM_SMEM>>>(a_h, a_l, f2_h, f2_l, ffb2, x1, out, nullptr, nullptr, ROWS, 512, FFD);
}

// round 5
// speedup vs baseline: 3.0444x; 1.0770x over previous
#include <cuda_runtime.h>
#include <cuda_bf16.h>
#include <math.h>
#include <stdint.h>

typedef __nv_bfloat16 bf16;

#define BB   8
#define LL   1024
#define SS   77
#define DD   512
#define HH   8
#define DHD  64
#define CDIM 768
#define FFD  2048
#define ROWS  (BB*LL)   /* 8192 */
#define CROWS (BB*SS)   /* 616  */

#define MB (1024u*1024u)
__device__ __align__(256) unsigned char g_scratch[448u*MB];

extern __shared__ __align__(16) unsigned char dynsmem[];

// ---------------------------------------------------------------------------
// helpers
// ---------------------------------------------------------------------------
__device__ __forceinline__ uint32_t pack2(bf16 a, bf16 b) {
    __nv_bfloat162 t(a, b);
    return *(uint32_t*)&t;
}
__device__ __forceinline__ void split2(float x, float y, uint32_t& h, uint32_t& l) {
    bf16 hx = __float2bfloat16(x), hy = __float2bfloat16(y);
    bf16 lx = __float2bfloat16(x - __bfloat162float(hx));
    bf16 ly = __float2bfloat16(y - __bfloat162float(hy));
    h = pack2(hx, hy);
    l = pack2(lx, ly);
}
__device__ __forceinline__ void cp16(uint32_t dst, const void* src, int srcsize) {
    asm volatile("cp.async.cg.shared.global [%0], [%1], 16, %2;\n"
                 :: "r"(dst), "l"(src), "r"(srcsize));
}
__device__ __forceinline__ void cp_commit() {
    asm volatile("cp.async.commit_group;\n" ::: "memory");
}
__device__ __forceinline__ void cp_wait1() {
    asm volatile("cp.async.wait_group 1;\n" ::: "memory");
}
__device__ __forceinline__ void cp_wait0() {
    asm volatile("cp.async.wait_group 0;\n" ::: "memory");
}

#define LDMX4(r0, r1, r2, r3, addr)                                            \
    asm volatile("ldmatrix.sync.aligned.m8n8.x4.shared.b16 {%0,%1,%2,%3}, [%4];"\
                 : "=r"(r0), "=r"(r1), "=r"(r2), "=r"(r3) : "r"(addr))

#define MMA_BF16(d, a0, a1, a2, a3, b0, b1)                                      \
    asm volatile("mma.sync.aligned.m16n8k16.row.col.f32.bf16.bf16.f32 "          \
                 "{%0,%1,%2,%3},{%4,%5,%6,%7},{%8,%9},{%0,%1,%2,%3};"            \
                 : "+f"(d[0]), "+f"(d[1]), "+f"(d[2]), "+f"(d[3])                 \
                 : "r"(a0), "r"(a1), "r"(a2), "r"(a3), "r"(b0), "r"(b1))

// ---------------------------------------------------------------------------
// LayerNorm: fp32 in -> (hi, lo) bf16 out
// ---------------------------------------------------------------------------
__global__ void ln_kernel(const float* __restrict__ x, const float* __restrict__ gamma,
                          const float* __restrict__ beta,
                          bf16* __restrict__ oh, bf16* __restrict__ ol)
{
    int row = blockIdx.x;
    const float* xr = x + (long)row * DD;
    int t = threadIdx.x;

    float v[4];
    float s = 0.f;
#pragma unroll
    for (int i = 0; i < 4; i++) { v[i] = xr[t + i*128]; s += v[i]; }

    __shared__ float red[4];
    __shared__ float red2[4];
#pragma unroll
    for (int off = 16; off; off >>= 1) s += __shfl_xor_sync(0xffffffffu, s, off);
    if ((t & 31) == 0) red[t >> 5] = s;
    __syncthreads();
    float mean = (red[0] + red[1] + red[2] + red[3]) * (1.f/512.f);

    float sq = 0.f;
#pragma unroll
    for (int i = 0; i < 4; i++) { float d = v[i] - mean; sq += d*d; }
#pragma unroll
    for (int off = 16; off; off >>= 1) sq += __shfl_xor_sync(0xffffffffu, sq, off);
    if ((t & 31) == 0) red2[t >> 5] = sq;
    __syncthreads();
    float var = (red2[0] + red2[1] + red2[2] + red2[3]) * (1.f/512.f);
    float rstd = rsqrtf(var + 1e-5f);

#pragma unroll
    for (int i = 0; i < 4; i++) {
        int c = t + i*128;
        float y = (v[i] - mean) * rstd * gamma[c] + beta[c];
        bf16 h = __float2bfloat16(y);
        oh[(long)row * DD + c] = h;
        ol[(long)row * DD + c] = __float2bfloat16(y - __bfloat162float(h));
    }
}

// ---------------------------------------------------------------------------
// fp32 -> (bf16 hi, bf16 lo) elementwise split (ctx only)
// ---------------------------------------------------------------------------
__global__ void split_kernel(const float* __restrict__ in, bf16* __restrict__ hi,
                             bf16* __restrict__ lo, int n)
{
    int i = blockIdx.x * blockDim.x + threadIdx.x;
    if (i >= n) return;
    float x = in[i];
    bf16 h = __float2bfloat16(x);
    hi[i] = h;
    lo[i] = __float2bfloat16(x - __bfloat162float(h));
}

// ---------------------------------------------------------------------------
// W[K,N] fp32 -> WT_hi[N,K], WT_lo[N,K] bf16 (tiled transpose + split)
// ---------------------------------------------------------------------------
__global__ void tsplit_kernel(const float* __restrict__ W, bf16* __restrict__ Th,
                              bf16* __restrict__ Tl, int K, int N)
{
    __shared__ float t[32][33];
    int k0 = blockIdx.y * 32, n0 = blockIdx.x * 32;
    int x = threadIdx.x, y = threadIdx.y; // 32 x 8
#pragma unroll
    for (int i = 0; i < 32; i += 8)
        t[y + i][x] = W[(size_t)(k0 + y + i) * N + n0 + x];
    __syncthreads();
#pragma unroll
    for (int i = 0; i < 32; i += 8) {
        float v = t[x][y + i];
        bf16 h = __float2bfloat16(v);
        bf16 l = __float2bfloat16(v - __bfloat162float(h));
        size_t o = (size_t)(n0 + y + i) * K + k0 + x;
        Th[o] = h; Tl[o] = l;
    }
}

// ---------------------------------------------------------------------------
// bf16-split tensor-core GEMM, ldmatrix edition:
//   C[M,N] = A[M,K] @ B^T, B pre-transposed [N,K]
//   C = Ah*Bh + Ah*Bl + Al*Bh  (fp32 accumulate)
// Block 128x128x32, 256 threads (8 warps, 2x4), warp tile 64x32,
// 2-stage cp.async pipeline (80KB smem -> 2 blocks/SM).
// Epilogue: Ch!=null -> (hi,lo) split out (+bias); else fp32 (+bias)(+res).
// ---------------------------------------------------------------------------
#define BKC 32
#define LDA 40
#define ST_ELE (4*128*LDA)
#define S_AH 0
#define S_AL (128*LDA)
#define S_BH (2*128*LDA)
#define S_BL (3*128*LDA)
#define NSTAGE 2
#define GEMM_SMEM (NSTAGE * ST_ELE * 2)

__global__ void __launch_bounds__(256)
gemm_mma(const bf16* __restrict__ Ah, const bf16* __restrict__ Al,
         const bf16* __restrict__ Bh, const bf16* __restrict__ Bl,
         const float* __restrict__ bias, const float* __restrict__ res,
         float* __restrict__ C, bf16* __restrict__ Ch, bf16* __restrict__ Cl,
         int M, int N, int K)
{
    bf16* sm = (bf16*)dynsmem;
    uint32_t smb = (uint32_t)__cvta_generic_to_shared(sm);

    int tid = threadIdx.x;
    int m0 = blockIdx.y * 128, n0 = blockIdx.x * 128;
    int wid = tid >> 5, lane = tid & 31;
    int wm = (wid & 1) * 64, wn = (wid >> 1) * 32;
    int g = lane >> 2, tq = lane & 3;

    float c[4][4][4];
#pragma unroll
    for (int i = 0; i < 4; i++)
#pragma unroll
        for (int j = 0; j < 4; j++)
#pragma unroll
            for (int r = 0; r < 4; r++) c[i][j][r] = 0.f;

    // ldmatrix source addresses (element offsets within a stage)
    // A x4: rows wm+mb*16+(lane&15), k byte group (lane>>4)*8
    uint32_t aoff = (uint32_t)((wm + (lane & 15)) * LDA + (lane >> 4) * 8) * 2;
    // B x4: rows wn+p*16+((lane>>4)&1)*8+(lane&7), k group ((lane>>3)&1)*8
    uint32_t boff = (uint32_t)((wn + ((lane >> 4) & 1) * 8 + (lane & 7)) * LDA
                               + ((lane >> 3) & 1) * 8) * 2;

    // staging mapping: thread covers rows r0, r0+64 at k-chunk kc (8 bf16)
    int r0 = tid >> 2, kc = tid & 3;
    int mA0 = m0 + r0, mA1 = m0 + r0 + 64;
    int szA0 = (mA0 < M) ? 16 : 0;
    int szA1 = (mA1 < M) ? 16 : 0;
    const bf16* pAh0 = Ah + (size_t)min(mA0, M-1) * K + kc*8;
    const bf16* pAh1 = Ah + (size_t)min(mA1, M-1) * K + kc*8;
    const bf16* pAl0 = Al + (size_t)min(mA0, M-1) * K + kc*8;
    const bf16* pAl1 = Al + (size_t)min(mA1, M-1) * K + kc*8;
    const bf16* pBh0 = Bh + (size_t)(n0 + r0) * K + kc*8;
    const bf16* pBh1 = Bh + (size_t)(n0 + r0 + 64) * K + kc*8;
    const bf16* pBl0 = Bl + (size_t)(n0 + r0) * K + kc*8;
    const bf16* pBl1 = Bl + (size_t)(n0 + r0 + 64) * K + kc*8;
    uint32_t dA0 = smb + (uint32_t)(S_AH + r0*LDA + kc*8) * 2;
    uint32_t dA1 = smb + (uint32_t)(S_AH + (r0+64)*LDA + kc*8) * 2;
    uint32_t dL0 = smb + (uint32_t)(S_AL + r0*LDA + kc*8) * 2;
    uint32_t dL1 = smb + (uint32_t)(S_AL + (r0+64)*LDA + kc*8) * 2;
    uint32_t dB0 = smb + (uint32_t)(S_BH + r0*LDA + kc*8) * 2;
    uint32_t dB1 = smb + (uint32_t)(S_BH + (r0+64)*LDA + kc*8) * 2;
    uint32_t dC0 = smb + (uint32_t)(S_BL + r0*LDA + kc*8) * 2;
    uint32_t dC1 = smb + (uint32_t)(S_BL + (r0+64)*LDA + kc*8) * 2;

#define LOAD_STAGE(s, k0v)                                                     \
    do {                                                                       \
        uint32_t so = (uint32_t)(s) * (ST_ELE * 2);                            \
        cp16(dA0 + so, pAh0 + (k0v), szA0);                                    \
        cp16(dA1 + so, pAh1 + (k0v), szA1);                                    \
        cp16(dL0 + so, pAl0 + (k0v), szA0);                                    \
        cp16(dL1 + so, pAl1 + (k0v), szA1);                                    \
        cp16(dB0 + so, pBh0 + (k0v), 16);                                      \
        cp16(dB1 + so, pBh1 + (k0v), 16);                                      \
        cp16(dC0 + so, pBl0 + (k0v), 16);                                      \
        cp16(dC1 + so, pBl1 + (k0v), 16);                                      \
        cp_commit();                                                           \
    } while (0)

    int nk = K / BKC;
    LOAD_STAGE(0, 0);
    LOAD_STAGE(1, BKC);

    for (int kt = 0; kt < nk; kt++) {
        if (kt + 2 <= nk) cp_wait1(); else cp_wait0();
        __syncthreads();
        uint32_t sbase = smb + (uint32_t)(kt & 1) * (ST_ELE * 2);

#pragma unroll
        for (int kk = 0; kk < BKC; kk += 16) {
            uint32_t ah[4][4], al[4][4], bh[4][2], bl[4][2];
#pragma unroll
            for (int mb = 0; mb < 4; mb++) {
                uint32_t ra = sbase + aoff + (uint32_t)(mb*16*LDA + kk) * 2;
                LDMX4(ah[mb][0], ah[mb][1], ah[mb][2], ah[mb][3], ra + S_AH*2);
                LDMX4(al[mb][0], al[mb][1], al[mb][2], al[mb][3], ra + S_AL*2);
            }
#pragma unroll
            for (int p = 0; p < 2; p++) {
                uint32_t rb = sbase + boff + (uint32_t)(p*16*LDA + kk) * 2;
                LDMX4(bh[2*p][0], bh[2*p][1], bh[2*p+1][0], bh[2*p+1][1], rb + S_BH*2);
                LDMX4(bl[2*p][0], bl[2*p][1], bl[2*p+1][0], bl[2*p+1][1], rb + S_BL*2);
            }
#pragma unroll
            for (int mb = 0; mb < 4; mb++)
#pragma unroll
                for (int nb = 0; nb < 4; nb++) {
                    MMA_BF16(c[mb][nb], ah[mb][0], ah[mb][1], ah[mb][2], ah[mb][3], bh[nb][0], bh[nb][1]);
                    MMA_BF16(c[mb][nb], ah[mb][0], ah[mb][1], ah[mb][2], ah[mb][3], bl[nb][0], bl[nb][1]);
                    MMA_BF16(c[mb][nb], al[mb][0], al[mb][1], al[mb][2], al[mb][3], bh[nb][0], bh[nb][1]);
                }
        }
        __syncthreads();
        if (kt + 2 < nk) LOAD_STAGE(kt & 1, (kt + 2) * BKC);
    }

    // epilogue
#pragma unroll
    for (int mb = 0; mb < 4; mb++) {
#pragma unroll
        for (int nb = 0; nb < 4; nb++) {
            int m = m0 + wm + mb*16 + g;
            int n = n0 + wn + nb*8 + tq*2;
            float b0 = bias ? bias[n]   : 0.f;
            float b1 = bias ? bias[n+1] : 0.f;
            if (Ch) {
                if (m < M) {
                    size_t idx = (size_t)m * N + n;
                    uint32_t hh, ll;
                    split2(c[mb][nb][0] + b0, c[mb][nb][1] + b1, hh, ll);
                    *(uint32_t*)&Ch[idx] = hh;
                    *(uint32_t*)&Cl[idx] = ll;
                }
                if (m + 8 < M) {
                    size_t idx = (size_t)(m+8) * N + n;
                    uint32_t hh, ll;
                    split2(c[mb][nb][2] + b0, c[mb][nb][3] + b1, hh, ll);
                    *(uint32_t*)&Ch[idx] = hh;
                    *(uint32_t*)&Cl[idx] = ll;
                }
            } else {
                if (m < M) {
                    size_t idx = (size_t)m * N + n;
                    float v0 = c[mb][nb][0] + b0;
                    float v1 = c[mb][nb][1] + b1;
                    if (res) { v0 += res[idx]; v1 += res[idx+1]; }
                    C[idx] = v0; C[idx+1] = v1;
                }
                if (m + 8 < M) {
                    size_t idx = (size_t)(m+8) * N + n;
                    float v0 = c[mb][nb][2] + b0;
                    float v1 = c[mb][nb][3] + b1;
                    if (res) { v0 += res[idx]; v1 += res[idx+1]; }
                    C[idx] = v0; C[idx+1] = v1;
                }
            }
        }
    }
#undef LOAD_STAGE
}

// ---------------------------------------------------------------------------
// Flash-style attention, bf16-split MMA, online softmax.
// Strides parametrized so fused QKV / KV buffers are read in place.
// ---------------------------------------------------------------------------
#define ATT_LD 72
#define AQ_H 0
#define AQ_L (64*ATT_LD)
#define AK_H (2*64*ATT_LD)
#define AK_L (3*64*ATT_LD)
#define AV_H (4*64*ATT_LD)
#define AV_L (5*64*ATT_LD)
#define ATT_SMEM (6*64*ATT_LD*2)

__global__ void __launch_bounds__(128)
attn_mma(const bf16* __restrict__ Qh, const bf16* __restrict__ Ql,
         const bf16* __restrict__ Kh, const bf16* __restrict__ Kl,
         const bf16* __restrict__ Vh, const bf16* __restrict__ Vl,
         bf16* __restrict__ Oh, bf16* __restrict__ Ol,
         int Lk, int kvL, int qStride, int kvStride)
{
    bf16* sm = (bf16*)dynsmem;
    int b = blockIdx.z, hh = blockIdx.y, q0 = blockIdx.x * 64;
    int tid = threadIdx.x;
    int wid = tid >> 5, lane = tid & 31;
    int g = lane >> 2, tq = lane & 3;
    int wm = wid * 16;

    for (int i = tid; i < 64*64; i += 128) {
        int qq = i >> 6, d = i & 63;
        size_t gidx = (size_t)(b*LL + q0 + qq) * qStride + hh*DHD + d;
        sm[AQ_H + qq*ATT_LD + d] = __float2bfloat16(__bfloat162float(Qh[gidx]) * 0.125f);
        sm[AQ_L + qq*ATT_LD + d] = __float2bfloat16(__bfloat162float(Ql[gidx]) * 0.125f);
    }
    __syncthreads();

    uint32_t qa_h[4][4], qa_l[4][4];
#pragma unroll
    for (int ks = 0; ks < 4; ks++) {
        const bf16* ph = sm + AQ_H + (wm + g)*ATT_LD + ks*16 + tq*2;
        const bf16* pl = sm + AQ_L + (wm + g)*ATT_LD + ks*16 + tq*2;
        qa_h[ks][0] = *(const uint32_t*)(ph);
        qa_h[ks][1] = *(const uint32_t*)(ph + 8*ATT_LD);
        qa_h[ks][2] = *(const uint32_t*)(ph + 8);
        qa_h[ks][3] = *(const uint32_t*)(ph + 8*ATT_LD + 8);
        qa_l[ks][0] = *(const uint32_t*)(pl);
        qa_l[ks][1] = *(const uint32_t*)(pl + 8*ATT_LD);
        qa_l[ks][2] = *(const uint32_t*)(pl + 8);
        qa_l[ks][3] = *(const uint32_t*)(pl + 8*ATT_LD + 8);
    }

    float mr[2] = {-1e30f, -1e30f};
    float lr[2] = {0.f, 0.f};
    float co[8][4];
#pragma unroll
    for (int nb = 0; nb < 8; nb++)
#pragma unroll
        for (int r = 0; r < 4; r++) co[nb][r] = 0.f;

    for (int kt = 0; kt < Lk; kt += 64) {
        __syncthreads();
        for (int i = tid; i < 64*64; i += 128) {
            int kk = i >> 6, d = i & 63;
            int krow = kt + kk;
            if (krow < Lk) {
                size_t gidx = (size_t)(b*kvL + krow) * kvStride + hh*DHD + d;
                sm[AK_H + kk*ATT_LD + d] = Kh[gidx];
                sm[AK_L + kk*ATT_LD + d] = Kl[gidx];
                sm[AV_H + d*ATT_LD + kk] = Vh[gidx];
                sm[AV_L + d*ATT_LD + kk] = Vl[gidx];
            } else {
                bf16 z = __float2bfloat16(0.f);
                sm[AK_H + kk*ATT_LD + d] = z;
                sm[AK_L + kk*ATT_LD + d] = z;
                sm[AV_H + d*ATT_LD + kk] = z;
                sm[AV_L + d*ATT_LD + kk] = z;
            }
        }
        __syncthreads();

        float s[8][4];
#pragma unroll
        for (int nb = 0; nb < 8; nb++) {
#pragma unroll
            for (int r = 0; r < 4; r++) s[nb][r] = 0.f;
#pragma unroll
            for (int ks = 0; ks < 4; ks++) {
                const bf16* ph = sm + AK_H + (nb*8 + g)*ATT_LD + ks*16 + tq*2;
                const bf16* pl = sm + AK_L + (nb*8 + g)*ATT_LD + ks*16 + tq*2;
                uint32_t kb0 = *(const uint32_t*)(ph);
                uint32_t kb1 = *(const uint32_t*)(ph + 8);
                uint32_t kl0 = *(const uint32_t*)(pl);
                uint32_t kl1 = *(const uint32_t*)(pl + 8);
                MMA_BF16(s[nb], qa_h[ks][0], qa_h[ks][1], qa_h[ks][2], qa_h[ks][3], kb0, kb1);
                MMA_BF16(s[nb], qa_h[ks][0], qa_h[ks][1], qa_h[ks][2], qa_h[ks][3], kl0, kl1);
                MMA_BF16(s[nb], qa_l[ks][0], qa_l[ks][1], qa_l[ks][2], qa_l[ks][3], kb0, kb1);
            }
        }

        if (kt + 64 > Lk) {
#pragma unroll
            for (int nb = 0; nb < 8; nb++) {
                int key = kt + nb*8 + tq*2;
                if (key     >= Lk) { s[nb][0] = -1e30f; s[nb][2] = -1e30f; }
                if (key + 1 >= Lk) { s[nb][1] = -1e30f; s[nb][3] = -1e30f; }
            }
        }

#pragma unroll
        for (int r = 0; r < 2; r++) {
            int i0 = 2*r, i1 = 2*r + 1;
            float tm = -1e30f;
#pragma unroll
            for (int nb = 0; nb < 8; nb++)
                tm = fmaxf(tm, fmaxf(s[nb][i0], s[nb][i1]));
            tm = fmaxf(tm, __shfl_xor_sync(0xffffffffu, tm, 1));
            tm = fmaxf(tm, __shfl_xor_sync(0xffffffffu, tm, 2));
            float mnew = fmaxf(mr[r], tm);
            float alpha = __expf(mr[r] - mnew);
            mr[r] = mnew;
            float sum = 0.f;
#pragma unroll
            for (int nb = 0; nb < 8; nb++) {
                s[nb][i0] = __expf(s[nb][i0] - mnew); sum += s[nb][i0];
                s[nb][i1] = __expf(s[nb][i1] - mnew); sum += s[nb][i1];
            }
            sum += __shfl_xor_sync(0xffffffffu, sum, 1);
            sum += __shfl_xor_sync(0xffffffffu, sum, 2);
            lr[r] = lr[r] * alpha + sum;
#pragma unroll
            for (int nb = 0; nb < 8; nb++) { co[nb][i0] *= alpha; co[nb][i1] *= alpha; }
        }

#pragma unroll
        for (int ks = 0; ks < 4; ks++) {
            uint32_t a_h[4], a_l[4];
            split2(s[2*ks  ][0], s[2*ks  ][1], a_h[0], a_l[0]);
            split2(s[2*ks  ][2], s[2*ks  ][3], a_h[1], a_l[1]);
            split2(s[2*ks+1][0], s[2*ks+1][1], a_h[2], a_l[2]);
            split2(s[2*ks+1][2], s[2*ks+1][3], a_h[3], a_l[3]);
#pragma unroll
            for (int nb = 0; nb < 8; nb++) {
                const bf16* ph = sm + AV_H + (nb*8 + g)*ATT_LD + ks*16 + tq*2;
                const bf16* pl = sm + AV_L + (nb*8 + g)*ATT_LD + ks*16 + tq*2;
                uint32_t vb0 = *(const uint32_t*)(ph);
                uint32_t vb1 = *(const uint32_t*)(ph + 8);
                uint32_t vl0 = *(const uint32_t*)(pl);
                uint32_t vl1 = *(const uint32_t*)(pl + 8);
                MMA_BF16(co[nb], a_h[0], a_h[1], a_h[2], a_h[3], vb0, vb1);
                MMA_BF16(co[nb], a_h[0], a_h[1], a_h[2], a_h[3], vl0, vl1);
                MMA_BF16(co[nb], a_l[0], a_l[1], a_l[2], a_l[3], vb0, vb1);
            }
        }
    }

    float inv0 = 1.f / lr[0], inv1 = 1.f / lr[1];
    int row0 = q0 + wm + g;
    size_t base0 = (size_t)(b*LL + row0) * DD + hh*DHD;
    size_t base1 = base0 + (size_t)8 * DD;
#pragma unroll
    for (int nb = 0; nb < 8; nb++) {
        int col = nb*8 + tq*2;
        uint32_t hh0, ll0, hh1, ll1;
        split2(co[nb][0]*inv0, co[nb][1]*inv0, hh0, ll0);
        split2(co[nb][2]*inv1, co[nb][3]*inv1, hh1, ll1);
        *(uint32_t*)&Oh[base0 + col] = hh0;
        *(uint32_t*)&Ol[base0 + col] = ll0;
        *(uint32_t*)&Oh[base1 + col] = hh1;
        *(uint32_t*)&Ol[base1 + col] = ll1;
    }
}

// ---------------------------------------------------------------------------
// GEGLU: (hi,lo) in -> (hi,lo) out
// ---------------------------------------------------------------------------
__global__ void geglu_kernel(const bf16* __restrict__ ph, const bf16* __restrict__ pl,
                             bf16* __restrict__ ah, bf16* __restrict__ al)
{
    long i = (long)blockIdx.x * blockDim.x + threadIdx.x;
    long row = i / FFD, col = i - row * FFD;
    long iv = row * (2*FFD) + col;
    long ig = iv + FFD;
    float val  = __bfloat162float(ph[iv]) + __bfloat162float(pl[iv]);
    float gate = __bfloat162float(ph[ig]) + __bfloat162float(pl[ig]);
    float r = val * gate * normcdff(gate);
    bf16 h = __float2bfloat16(r);
    ah[i] = h;
    al[i] = __float2bfloat16(r - __bfloat162float(h));
}

// ---------------------------------------------------------------------------
extern "C" void kernel_launch(void* const* d_in, const int* in_sizes, int n_in,
                              void* d_out, int out_size)
{
    const float* x    = (const float*)d_in[0];
    const float* ctx  = (const float*)d_in[1];
    const float* ln1g = (const float*)d_in[2];
    const float* ln1b = (const float*)d_in[3];
    const float* ln2g = (const float*)d_in[4];
    const float* ln2b = (const float*)d_in[5];
    const float* ln3g = (const float*)d_in[6];
    const float* ln3b = (const float*)d_in[7];
    const float* a1wq = (const float*)d_in[8];
    const float* a1wk = (const float*)d_in[9];
    const float* a1wv = (const float*)d_in[10];
    const float* a1wo = (const float*)d_in[11];
    const float* a1bo = (const float*)d_in[12];
    const float* a2wq = (const float*)d_in[13];
    const float* a2wk = (const float*)d_in[14];
    const float* a2wv = (const float*)d_in[15];
    const float* a2wo = (const float*)d_in[16];
    const float* a2bo = (const float*)d_in[17];
    const float* ffw1 = (const float*)d_in[18];
    const float* ffb1 = (const float*)d_in[19];
    const float* ffw2 = (const float*)d_in[20];
    const float* ffb2 = (const float*)d_in[21];
    float* out = (float*)d_out;

    unsigned char* base = nullptr;
    cudaGetSymbolAddress((void**)&base, g_scratch);

    bf16* h_h   = (bf16*)(base + 0u*MB);     // 8 MB  [8192,512]
    bf16* h_l   = (bf16*)(base + 8u*MB);
    bf16* qkv_h = (bf16*)(base + 16u*MB);    // 24 MB [8192,1536]
    bf16* qkv_l = (bf16*)(base + 40u*MB);
    bf16* q_h   = (bf16*)(base + 64u*MB);    // 8 MB  [8192,512] (cross q)
    bf16* q_l   = (bf16*)(base + 72u*MB);
    bf16* kv_h  = (bf16*)(base + 80u*MB);    // ~1.3MB [616,1024]
    bf16* kv_l  = (bf16*)(base + 82u*MB);
    bf16* o_h   = (bf16*)(base + 84u*MB);    // 8 MB  [8192,512]
    bf16* o_l   = (bf16*)(base + 92u*MB);
    float* x1   = (float*)(base + 100u*MB);  // 16 MB
    bf16* p_h   = (bf16*)(base + 116u*MB);   // 64 MB [8192,4096]
    bf16* p_l   = (bf16*)(base + 180u*MB);
    bf16* a_h   = (bf16*)(base + 244u*MB);   // 32 MB [8192,2048]
    bf16* a_l   = (bf16*)(base + 276u*MB);
    bf16* cx_h  = (bf16*)(base + 308u*MB);
    bf16* cx_l  = (bf16*)(base + 310u*MB);
    bf16* wcur  = (bf16*)(base + 312u*MB);

    // fused weight buffers
    bf16 *w1qkv_h, *w1qkv_l, *w1o_h, *w1o_l;
    bf16 *w2q_h, *w2q_l, *w2kv_h, *w2kv_l, *w2o_h, *w2o_l;
    bf16 *f1_h, *f1_l, *f2_h, *f2_l;
    {
        size_t cur = 0;
        auto al2 = [&](size_t n, bf16** hh, bf16** ll) {
            *hh = wcur + cur; cur += n; *ll = wcur + cur; cur += n;
        };
        al2(1536*512, &w1qkv_h, &w1qkv_l);   // q|k|v stacked in N
        al2(512*512,  &w1o_h, &w1o_l);
        al2(512*512,  &w2q_h, &w2q_l);
        al2(1024*768, &w2kv_h, &w2kv_l);     // k|v stacked in N
        al2(512*512,  &w2o_h, &w2o_l);
        al2(512*4096, &f1_h,  &f1_l);
        al2(2048*512, &f2_h,  &f2_l);
    }

    static bool attr_set = false;
    if (!attr_set) {
        cudaFuncSetAttribute(gemm_mma, cudaFuncAttributeMaxDynamicSharedMemorySize, GEMM_SMEM);
        cudaFuncSetAttribute(attn_mma, cudaFuncAttributeMaxDynamicSharedMemorySize, ATT_SMEM);
        attr_set = true;
    }

    dim3 tb(32, 8);
    tsplit_kernel<<<dim3(512/32, 512/32), tb>>>(a1wq, w1qkv_h,              w1qkv_l,              512, 512);
    tsplit_kernel<<<dim3(512/32, 512/32), tb>>>(a1wk, w1qkv_h + 512*512,    w1qkv_l + 512*512,    512, 512);
    tsplit_kernel<<<dim3(512/32, 512/32), tb>>>(a1wv, w1qkv_h + 2*512*512,  w1qkv_l + 2*512*512,  512, 512);
    tsplit_kernel<<<dim3(512/32, 512/32), tb>>>(a1wo, w1o_h, w1o_l, 512, 512);
    tsplit_kernel<<<dim3(512/32, 512/32), tb>>>(a2wq, w2q_h, w2q_l, 512, 512);
    tsplit_kernel<<<dim3(512/32, 768/32), tb>>>(a2wk, w2kv_h,            w2kv_l,            768, 512);
    tsplit_kernel<<<dim3(512/32, 768/32), tb>>>(a2wv, w2kv_h + 512*768,  w2kv_l + 512*768,  768, 512);
    tsplit_kernel<<<dim3(512/32, 512/32), tb>>>(a2wo, w2o_h, w2o_l, 512, 512);
    tsplit_kernel<<<dim3(4096/32, 512/32), tb>>>(ffw1, f1_h, f1_l, 512, 4096);
    tsplit_kernel<<<dim3(512/32, 2048/32), tb>>>(ffw2, f2_h, f2_l, 2048, 512);
    split_kernel<<<(CROWS*CDIM + 255)/256, 256>>>(ctx, cx_h, cx_l, CROWS*CDIM);

    dim3 gQKV(1536/128, ROWS/128);       // (12, 64)
    dim3 g512(512/128, ROWS/128);        // (4, 64)
    dim3 gKV(1024/128, (CROWS+127)/128); // (8, 5)
    dim3 gFF1(4096/128, ROWS/128);       // (32, 64)
    dim3 gattn(LL/64, HH, BB);

    // --- self attention block ---
    ln_kernel<<<ROWS, 128>>>(x, ln1g, ln1b, h_h, h_l);
    gemm_mma<<<gQKV, 256, GEMM_SMEM>>>(h_h, h_l, w1qkv_h, w1qkv_l, nullptr, nullptr, nullptr, qkv_h, qkv_l, ROWS, 1536, 512);
    attn_mma<<<gattn, 128, ATT_SMEM>>>(qkv_h, qkv_l, qkv_h + 512, qkv_l + 512, qkv_h + 1024, qkv_l + 1024,
                                       o_h, o_l, LL, LL, 1536, 1536);
    gemm_mma<<<g512, 256, GEMM_SMEM>>>(o_h, o_l, w1o_h, w1o_l, a1bo, x, x1, nullptr, nullptr, ROWS, 512, 512);

    // --- cross attention block ---
    ln_kernel<<<ROWS, 128>>>(x1, ln2g, ln2b, h_h, h_l);
    gemm_mma<<<g512, 256, GEMM_SMEM>>>(h_h, h_l, w2q_h, w2q_l, nullptr, nullptr, nullptr, q_h, q_l, ROWS, 512, 512);
    gemm_mma<<<gKV, 256, GEMM_SMEM>>>(cx_h, cx_l, w2kv_h, w2kv_l, nullptr, nullptr, nullptr, kv_h, kv_l, CROWS, 1024, 768);
    attn_mma<<<gattn, 128, ATT_SMEM>>>(q_h, q_l, kv_h, kv_l, kv_h + 512, kv_l + 512,
                                       o_h, o_l, SS, SS, 512, 1024);
    gemm_mma<<<g512, 256, GEMM_SMEM>>>(o_h, o_l, w2o_h, w2o_l, a2bo, x1, x1, nullptr, nullptr, ROWS, 512, 512);

    // --- GEGLU feed-forward ---
    ln_kernel<<<ROWS, 128>>>(x1, ln3g, ln3b, h_h, h_l);
    gemm_mma<<<gFF1, 256, GEMM_SMEM>>>(h_h, h_l, f1_h, f1_l, ffb1, nullptr, nullptr, p_h, p_l, ROWS, 4096, 512);
    geglu_kernel<<<(ROWS * FFD) / 256, 256>>>(p_h, p_l, a_h, a_l);
    gemm_mma<<<g512, 256, GEMM_SMEM>>>(a_h, a_l, f2_h, f2_l, ffb2, x1, out, nullptr, nullptr, ROWS, 512, FFD);
}

// round 6
// speedup vs baseline: 4.4860x; 1.4735x over previous
#include <cuda_runtime.h>
#include <cuda_bf16.h>
#include <math.h>
#include <stdint.h>

typedef __nv_bfloat16 bf16;

#define BB   8
#define LL   1024
#define SS   77
#define DD   512
#define HH   8
#define DHD  64
#define CDIM 768
#define FFD  2048
#define ROWS  (BB*LL)   /* 8192 */
#define CROWS (BB*SS)   /* 616  */

#define MB (1024u*1024u)
__device__ __align__(256) unsigned char g_scratch[448u*MB];

extern __shared__ __align__(16) unsigned char dynsmem[];

// ---------------------------------------------------------------------------
// helpers
// ---------------------------------------------------------------------------
__device__ __forceinline__ uint32_t pack2(bf16 a, bf16 b) {
    __nv_bfloat162 t(a, b);
    return *(uint32_t*)&t;
}
__device__ __forceinline__ void split2(float x, float y, uint32_t& h, uint32_t& l) {
    bf16 hx = __float2bfloat16(x), hy = __float2bfloat16(y);
    bf16 lx = __float2bfloat16(x - __bfloat162float(hx));
    bf16 ly = __float2bfloat16(y - __bfloat162float(hy));
    h = pack2(hx, hy);
    l = pack2(lx, ly);
}
__device__ __forceinline__ void cp16(uint32_t dst, const void* src, int srcsize) {
    asm volatile("cp.async.cg.shared.global [%0], [%1], 16, %2;\n"
                 :: "r"(dst), "l"(src), "r"(srcsize));
}
__device__ __forceinline__ void cp_commit() {
    asm volatile("cp.async.commit_group;\n" ::: "memory");
}
__device__ __forceinline__ void cp_wait1() {
    asm volatile("cp.async.wait_group 1;\n" ::: "memory");
}
__device__ __forceinline__ void cp_wait0() {
    asm volatile("cp.async.wait_group 0;\n" ::: "memory");
}

#define LDMX4(r0, r1, r2, r3, addr)                                            \
    asm volatile("ldmatrix.sync.aligned.m8n8.x4.shared.b16 {%0,%1,%2,%3}, [%4];"\
                 : "=r"(r0), "=r"(r1), "=r"(r2), "=r"(r3) : "r"(addr))

#define LDMT4(r0, r1, r2, r3, addr)                                            \
    asm volatile("ldmatrix.sync.aligned.m8n8.x4.trans.shared.b16 {%0,%1,%2,%3}, [%4];"\
                 : "=r"(r0), "=r"(r1), "=r"(r2), "=r"(r3) : "r"(addr))

#define MMA_BF16(d, a0, a1, a2, a3, b0, b1)                                      \
    asm volatile("mma.sync.aligned.m16n8k16.row.col.f32.bf16.bf16.f32 "          \
                 "{%0,%1,%2,%3},{%4,%5,%6,%7},{%8,%9},{%0,%1,%2,%3};"            \
                 : "+f"(d[0]), "+f"(d[1]), "+f"(d[2]), "+f"(d[3])                 \
                 : "r"(a0), "r"(a1), "r"(a2), "r"(a3), "r"(b0), "r"(b1))

// ---------------------------------------------------------------------------
// LayerNorm: fp32 in -> (hi, lo) bf16 out  (vectorized)
// ---------------------------------------------------------------------------
__global__ void ln_kernel(const float* __restrict__ x, const float* __restrict__ gamma,
                          const float* __restrict__ beta,
                          bf16* __restrict__ oh, bf16* __restrict__ ol)
{
    int row = blockIdx.x;
    int t = threadIdx.x;
    float4 v = ((const float4*)(x + (long)row * DD))[t];

    float s = v.x + v.y + v.z + v.w;
    __shared__ float red[4];
    __shared__ float red2[4];
#pragma unroll
    for (int off = 16; off; off >>= 1) s += __shfl_xor_sync(0xffffffffu, s, off);
    if ((t & 31) == 0) red[t >> 5] = s;
    __syncthreads();
    float mean = (red[0] + red[1] + red[2] + red[3]) * (1.f/512.f);

    float dx = v.x - mean, dy = v.y - mean, dz = v.z - mean, dw = v.w - mean;
    float sq = dx*dx + dy*dy + dz*dz + dw*dw;
#pragma unroll
    for (int off = 16; off; off >>= 1) sq += __shfl_xor_sync(0xffffffffu, sq, off);
    if ((t & 31) == 0) red2[t >> 5] = sq;
    __syncthreads();
    float var = (red2[0] + red2[1] + red2[2] + red2[3]) * (1.f/512.f);
    float rstd = rsqrtf(var + 1e-5f);

    float4 g4 = ((const float4*)gamma)[t];
    float4 b4 = ((const float4*)beta)[t];
    float y0 = dx * rstd * g4.x + b4.x;
    float y1 = dy * rstd * g4.y + b4.y;
    float y2 = dz * rstd * g4.z + b4.z;
    float y3 = dw * rstd * g4.w + b4.w;
    uint32_t h01, l01, h23, l23;
    split2(y0, y1, h01, l01);
    split2(y2, y3, h23, l23);
    uint2 hv = {h01, h23}, lv = {l01, l23};
    ((uint2*)(oh + (long)row * DD))[t] = hv;
    ((uint2*)(ol + (long)row * DD))[t] = lv;
}

// ---------------------------------------------------------------------------
// fp32 -> (bf16 hi, bf16 lo) elementwise split (ctx only)
// ---------------------------------------------------------------------------
__global__ void split_kernel(const float* __restrict__ in, bf16* __restrict__ hi,
                             bf16* __restrict__ lo, int n)
{
    int i = blockIdx.x * blockDim.x + threadIdx.x;
    if (i >= n) return;
    float x = in[i];
    bf16 h = __float2bfloat16(x);
    hi[i] = h;
    lo[i] = __float2bfloat16(x - __bfloat162float(h));
}

// ---------------------------------------------------------------------------
// W[K,N] fp32 -> WT_hi[N,K], WT_lo[N,K] bf16 (tiled transpose + split)
// ---------------------------------------------------------------------------
__global__ void tsplit_kernel(const float* __restrict__ W, bf16* __restrict__ Th,
                              bf16* __restrict__ Tl, int K, int N)
{
    __shared__ float t[32][33];
    int k0 = blockIdx.y * 32, n0 = blockIdx.x * 32;
    int x = threadIdx.x, y = threadIdx.y; // 32 x 8
#pragma unroll
    for (int i = 0; i < 32; i += 8)
        t[y + i][x] = W[(size_t)(k0 + y + i) * N + n0 + x];
    __syncthreads();
#pragma unroll
    for (int i = 0; i < 32; i += 8) {
        float v = t[x][y + i];
        bf16 h = __float2bfloat16(v);
        bf16 l = __float2bfloat16(v - __bfloat162float(h));
        size_t o = (size_t)(n0 + y + i) * K + k0 + x;
        Th[o] = h; Tl[o] = l;
    }
}

// ---------------------------------------------------------------------------
// bf16-split tensor-core GEMM, ldmatrix edition (unchanged from round 5)
// ---------------------------------------------------------------------------
#define BKC 32
#define LDA 40
#define ST_ELE (4*128*LDA)
#define S_AH 0
#define S_AL (128*LDA)
#define S_BH (2*128*LDA)
#define S_BL (3*128*LDA)
#define NSTAGE 2
#define GEMM_SMEM (NSTAGE * ST_ELE * 2)

__global__ void __launch_bounds__(256)
gemm_mma(const bf16* __restrict__ Ah, const bf16* __restrict__ Al,
         const bf16* __restrict__ Bh, const bf16* __restrict__ Bl,
         const float* __restrict__ bias, const float* __restrict__ res,
         float* __restrict__ C, bf16* __restrict__ Ch, bf16* __restrict__ Cl,
         int M, int N, int K)
{
    bf16* sm = (bf16*)dynsmem;
    uint32_t smb = (uint32_t)__cvta_generic_to_shared(sm);

    int tid = threadIdx.x;
    int m0 = blockIdx.y * 128, n0 = blockIdx.x * 128;
    int wid = tid >> 5, lane = tid & 31;
    int wm = (wid & 1) * 64, wn = (wid >> 1) * 32;
    int g = lane >> 2, tq = lane & 3;

    float c[4][4][4];
#pragma unroll
    for (int i = 0; i < 4; i++)
#pragma unroll
        for (int j = 0; j < 4; j++)
#pragma unroll
            for (int r = 0; r < 4; r++) c[i][j][r] = 0.f;

    uint32_t aoff = (uint32_t)((wm + (lane & 15)) * LDA + (lane >> 4) * 8) * 2;
    uint32_t boff = (uint32_t)((wn + ((lane >> 4) & 1) * 8 + (lane & 7)) * LDA
                               + ((lane >> 3) & 1) * 8) * 2;

    int r0 = tid >> 2, kc = tid & 3;
    int mA0 = m0 + r0, mA1 = m0 + r0 + 64;
    int szA0 = (mA0 < M) ? 16 : 0;
    int szA1 = (mA1 < M) ? 16 : 0;
    const bf16* pAh0 = Ah + (size_t)min(mA0, M-1) * K + kc*8;
    const bf16* pAh1 = Ah + (size_t)min(mA1, M-1) * K + kc*8;
    const bf16* pAl0 = Al + (size_t)min(mA0, M-1) * K + kc*8;
    const bf16* pAl1 = Al + (size_t)min(mA1, M-1) * K + kc*8;
    const bf16* pBh0 = Bh + (size_t)(n0 + r0) * K + kc*8;
    const bf16* pBh1 = Bh + (size_t)(n0 + r0 + 64) * K + kc*8;
    const bf16* pBl0 = Bl + (size_t)(n0 + r0) * K + kc*8;
    const bf16* pBl1 = Bl + (size_t)(n0 + r0 + 64) * K + kc*8;
    uint32_t dA0 = smb + (uint32_t)(S_AH + r0*LDA + kc*8) * 2;
    uint32_t dA1 = smb + (uint32_t)(S_AH + (r0+64)*LDA + kc*8) * 2;
    uint32_t dL0 = smb + (uint32_t)(S_AL + r0*LDA + kc*8) * 2;
    uint32_t dL1 = smb + (uint32_t)(S_AL + (r0+64)*LDA + kc*8) * 2;
    uint32_t dB0 = smb + (uint32_t)(S_BH + r0*LDA + kc*8) * 2;
    uint32_t dB1 = smb + (uint32_t)(S_BH + (r0+64)*LDA + kc*8) * 2;
    uint32_t dC0 = smb + (uint32_t)(S_BL + r0*LDA + kc*8) * 2;
    uint32_t dC1 = smb + (uint32_t)(S_BL + (r0+64)*LDA + kc*8) * 2;

#define LOAD_STAGE(s, k0v)                                                     \
    do {                                                                       \
        uint32_t so = (uint32_t)(s) * (ST_ELE * 2);                            \
        cp16(dA0 + so, pAh0 + (k0v), szA0);                                    \
        cp16(dA1 + so, pAh1 + (k0v), szA1);                                    \
        cp16(dL0 + so, pAl0 + (k0v), szA0);                                    \
        cp16(dL1 + so, pAl1 + (k0v), szA1);                                    \
        cp16(dB0 + so, pBh0 + (k0v), 16);                                      \
        cp16(dB1 + so, pBh1 + (k0v), 16);                                      \
        cp16(dC0 + so, pBl0 + (k0v), 16);                                      \
        cp16(dC1 + so, pBl1 + (k0v), 16);                                      \
        cp_commit();                                                           \
    } while (0)

    int nk = K / BKC;
    LOAD_STAGE(0, 0);
    LOAD_STAGE(1, BKC);

    for (int kt = 0; kt < nk; kt++) {
        if (kt + 2 <= nk) cp_wait1(); else cp_wait0();
        __syncthreads();
        uint32_t sbase = smb + (uint32_t)(kt & 1) * (ST_ELE * 2);

#pragma unroll
        for (int kk = 0; kk < BKC; kk += 16) {
            uint32_t ah[4][4], al[4][4], bh[4][2], bl[4][2];
#pragma unroll
            for (int mb = 0; mb < 4; mb++) {
                uint32_t ra = sbase + aoff + (uint32_t)(mb*16*LDA + kk) * 2;
                LDMX4(ah[mb][0], ah[mb][1], ah[mb][2], ah[mb][3], ra + S_AH*2);
                LDMX4(al[mb][0], al[mb][1], al[mb][2], al[mb][3], ra + S_AL*2);
            }
#pragma unroll
            for (int p = 0; p < 2; p++) {
                uint32_t rb = sbase + boff + (uint32_t)(p*16*LDA + kk) * 2;
                LDMX4(bh[2*p][0], bh[2*p][1], bh[2*p+1][0], bh[2*p+1][1], rb + S_BH*2);
                LDMX4(bl[2*p][0], bl[2*p][1], bl[2*p+1][0], bl[2*p+1][1], rb + S_BL*2);
            }
#pragma unroll
            for (int mb = 0; mb < 4; mb++)
#pragma unroll
                for (int nb = 0; nb < 4; nb++) {
                    MMA_BF16(c[mb][nb], ah[mb][0], ah[mb][1], ah[mb][2], ah[mb][3], bh[nb][0], bh[nb][1]);
                    MMA_BF16(c[mb][nb], ah[mb][0], ah[mb][1], ah[mb][2], ah[mb][3], bl[nb][0], bl[nb][1]);
                    MMA_BF16(c[mb][nb], al[mb][0], al[mb][1], al[mb][2], al[mb][3], bh[nb][0], bh[nb][1]);
                }
        }
        __syncthreads();
        if (kt + 2 < nk) LOAD_STAGE(kt & 1, (kt + 2) * BKC);
    }

#pragma unroll
    for (int mb = 0; mb < 4; mb++) {
#pragma unroll
        for (int nb = 0; nb < 4; nb++) {
            int m = m0 + wm + mb*16 + g;
            int n = n0 + wn + nb*8 + tq*2;
            float b0 = bias ? bias[n]   : 0.f;
            float b1 = bias ? bias[n+1] : 0.f;
            if (Ch) {
                if (m < M) {
                    size_t idx = (size_t)m * N + n;
                    uint32_t hh, ll;
                    split2(c[mb][nb][0] + b0, c[mb][nb][1] + b1, hh, ll);
                    *(uint32_t*)&Ch[idx] = hh;
                    *(uint32_t*)&Cl[idx] = ll;
                }
                if (m + 8 < M) {
                    size_t idx = (size_t)(m+8) * N + n;
                    uint32_t hh, ll;
                    split2(c[mb][nb][2] + b0, c[mb][nb][3] + b1, hh, ll);
                    *(uint32_t*)&Ch[idx] = hh;
                    *(uint32_t*)&Cl[idx] = ll;
                }
            } else {
                if (m < M) {
                    size_t idx = (size_t)m * N + n;
                    float v0 = c[mb][nb][0] + b0;
                    float v1 = c[mb][nb][1] + b1;
                    if (res) { v0 += res[idx]; v1 += res[idx+1]; }
                    C[idx] = v0; C[idx+1] = v1;
                }
                if (m + 8 < M) {
                    size_t idx = (size_t)(m+8) * N + n;
                    float v0 = c[mb][nb][2] + b0;
                    float v1 = c[mb][nb][3] + b1;
                    if (res) { v0 += res[idx]; v1 += res[idx+1]; }
                    C[idx] = v0; C[idx+1] = v1;
                }
            }
        }
    }
#undef LOAD_STAGE
}

// ---------------------------------------------------------------------------
// Flash attention v2: 256 threads, 128 q rows/block, cp.async double-buffered
// K/V, ldmatrix fragments, V via ldmatrix.trans (no transpose store).
// ---------------------------------------------------------------------------
#define ATT_LD 72
#define AQ_H 0
#define AQ_L (128*ATT_LD)
#define ASTG (2*128*ATT_LD)     /* 18432: start of K/V stages */
#define STG_SZ (4*64*ATT_LD)    /* 18432 elems per stage */
#define KH_O 0
#define KL_O (64*ATT_LD)
#define VH_O (2*64*ATT_LD)
#define VL_O (3*64*ATT_LD)
#define ATT_SMEM ((ASTG + 2*STG_SZ)*2)   /* 110592 bytes */

__global__ void __launch_bounds__(256, 2)
attn_mma(const bf16* __restrict__ Qh, const bf16* __restrict__ Ql,
         const bf16* __restrict__ Kh, const bf16* __restrict__ Kl,
         const bf16* __restrict__ Vh, const bf16* __restrict__ Vl,
         bf16* __restrict__ Oh, bf16* __restrict__ Ol,
         int Lk, int kvL, int qStride, int kvStride)
{
    bf16* sm = (bf16*)dynsmem;
    uint32_t smb = (uint32_t)__cvta_generic_to_shared(sm);
    int b = blockIdx.z, hh = blockIdx.y, q0 = blockIdx.x * 128;
    int tid = threadIdx.x;
    int wid = tid >> 5, lane = tid & 31;
    int g = lane >> 2, tq = lane & 3;
    int wm = wid * 16;

    // ---- Q load (scaled by 0.125, exact) ----
    {
        __nv_bfloat162 sc = __floats2bfloat162_rn(0.125f, 0.125f);
#pragma unroll
        for (int u = 0; u < 16; u++) {
            int i = tid + u*256;           // 4096 uint32 pairs
            int row = i >> 5, dp = (i & 31) * 2;
            size_t gq = (size_t)(b*LL + q0 + row) * qStride + hh*DHD + dp;
            __nv_bfloat162 th = __hmul2(*(const __nv_bfloat162*)(Qh + gq), sc);
            __nv_bfloat162 tl = __hmul2(*(const __nv_bfloat162*)(Ql + gq), sc);
            *(__nv_bfloat162*)&sm[AQ_H + row*ATT_LD + dp] = th;
            *(__nv_bfloat162*)&sm[AQ_L + row*ATT_LD + dp] = tl;
        }
    }

#define LOADKV(s, ktile)                                                      \
    do {                                                                      \
        int kb = (ktile) * 64;                                                \
        uint32_t so = (uint32_t)(ASTG + (s)*STG_SZ);                          \
        _Pragma("unroll")                                                     \
        for (int u = 0; u < 2; u++) {                                         \
            int rem = tid + u*256;                                            \
            int row = rem >> 3, ch = rem & 7;                                 \
            int krow = kb + row;                                              \
            int szk = (krow < Lk) ? 16 : 0;                                   \
            size_t gix = (size_t)(b*kvL + (szk ? krow : 0)) * kvStride        \
                         + hh*DHD + ch*8;                                     \
            uint32_t da = smb + (so + row*ATT_LD + ch*8) * 2;                 \
            cp16(da,           Kh + gix, szk);                                \
            cp16(da + KL_O*2,  Kl + gix, szk);                                \
            cp16(da + VH_O*2,  Vh + gix, szk);                                \
            cp16(da + VL_O*2,  Vl + gix, szk);                                \
        }                                                                     \
        cp_commit();                                                          \
    } while (0)

    int nkt = (Lk + 63) >> 6;
    LOADKV(0, 0);
    if (nkt > 1) LOADKV(1, 1);

    float mr[2] = {-1e30f, -1e30f};
    float lr[2] = {0.f, 0.f};
    float co[8][4];
#pragma unroll
    for (int nb = 0; nb < 8; nb++)
#pragma unroll
        for (int r = 0; r < 4; r++) co[nb][r] = 0.f;

    for (int kt = 0; kt < nkt; kt++) {
        if (kt + 2 <= nkt && nkt > 1) cp_wait1(); else cp_wait0();
        __syncthreads();
        uint32_t ss = (uint32_t)(ASTG + (kt & 1) * STG_SZ);

        // ---- S = Q K^T (3 split MMAs) ----
        float s[8][4];
#pragma unroll
        for (int nb = 0; nb < 8; nb++)
#pragma unroll
            for (int r = 0; r < 4; r++) s[nb][r] = 0.f;

#pragma unroll
        for (int ks = 0; ks < 4; ks++) {
            uint32_t qh[4], ql[4];
            uint32_t qa = smb + (uint32_t)((wm + (lane & 15))*ATT_LD
                                           + ks*16 + (lane >> 4)*8) * 2;
            LDMX4(qh[0], qh[1], qh[2], qh[3], qa + AQ_H*2);
            LDMX4(ql[0], ql[1], ql[2], ql[3], qa + AQ_L*2);
#pragma unroll
            for (int kp = 0; kp < 4; kp++) {
                uint32_t kh[4], kl[4];
                uint32_t ka = smb + (ss + (uint32_t)((kp*16 + ((lane>>4)&1)*8 + (lane&7))*ATT_LD
                                                     + ks*16 + ((lane>>3)&1)*8)) * 2;
                LDMX4(kh[0], kh[1], kh[2], kh[3], ka + KH_O*2);
                LDMX4(kl[0], kl[1], kl[2], kl[3], ka + KL_O*2);
                MMA_BF16(s[2*kp],   qh[0], qh[1], qh[2], qh[3], kh[0], kh[1]);
                MMA_BF16(s[2*kp],   qh[0], qh[1], qh[2], qh[3], kl[0], kl[1]);
                MMA_BF16(s[2*kp],   ql[0], ql[1], ql[2], ql[3], kh[0], kh[1]);
                MMA_BF16(s[2*kp+1], qh[0], qh[1], qh[2], qh[3], kh[2], kh[3]);
                MMA_BF16(s[2*kp+1], qh[0], qh[1], qh[2], qh[3], kl[2], kl[3]);
                MMA_BF16(s[2*kp+1], ql[0], ql[1], ql[2], ql[3], kh[2], kh[3]);
            }
        }

        // ---- mask tail keys ----
        if ((kt + 1) * 64 > Lk) {
#pragma unroll
            for (int nb = 0; nb < 8; nb++) {
                int key = kt*64 + nb*8 + tq*2;
                if (key     >= Lk) { s[nb][0] = -1e30f; s[nb][2] = -1e30f; }
                if (key + 1 >= Lk) { s[nb][1] = -1e30f; s[nb][3] = -1e30f; }
            }
        }

        // ---- online softmax ----
#pragma unroll
        for (int r = 0; r < 2; r++) {
            int i0 = 2*r, i1 = 2*r + 1;
            float tm = -1e30f;
#pragma unroll
            for (int nb = 0; nb < 8; nb++)
                tm = fmaxf(tm, fmaxf(s[nb][i0], s[nb][i1]));
            tm = fmaxf(tm, __shfl_xor_sync(0xffffffffu, tm, 1));
            tm = fmaxf(tm, __shfl_xor_sync(0xffffffffu, tm, 2));
            float mnew = fmaxf(mr[r], tm);
            float alpha = __expf(mr[r] - mnew);
            mr[r] = mnew;
            float sum = 0.f;
#pragma unroll
            for (int nb = 0; nb < 8; nb++) {
                s[nb][i0] = __expf(s[nb][i0] - mnew); sum += s[nb][i0];
                s[nb][i1] = __expf(s[nb][i1] - mnew); sum += s[nb][i1];
            }
            sum += __shfl_xor_sync(0xffffffffu, sum, 1);
            sum += __shfl_xor_sync(0xffffffffu, sum, 2);
            lr[r] = lr[r] * alpha + sum;
#pragma unroll
            for (int nb = 0; nb < 8; nb++) { co[nb][i0] *= alpha; co[nb][i1] *= alpha; }
        }

        // ---- O += P V (V fragments via ldmatrix.trans) ----
#pragma unroll
        for (int ks = 0; ks < 4; ks++) {
            uint32_t a_h[4], a_l[4];
            split2(s[2*ks  ][0], s[2*ks  ][1], a_h[0], a_l[0]);
            split2(s[2*ks  ][2], s[2*ks  ][3], a_h[1], a_l[1]);
            split2(s[2*ks+1][0], s[2*ks+1][1], a_h[2], a_l[2]);
            split2(s[2*ks+1][2], s[2*ks+1][3], a_h[3], a_l[3]);
#pragma unroll
            for (int np = 0; np < 4; np++) {
                uint32_t vh[4], vl[4];
                uint32_t va = smb + (ss + (uint32_t)(VH_O + (ks*16 + (lane & 15))*ATT_LD
                                                     + np*16 + ((lane >> 4) << 3))) * 2;
                LDMT4(vh[0], vh[1], vh[2], vh[3], va);
                LDMT4(vl[0], vl[1], vl[2], vl[3], va + (VL_O - VH_O)*2);
                MMA_BF16(co[2*np],   a_h[0], a_h[1], a_h[2], a_h[3], vh[0], vh[1]);
                MMA_BF16(co[2*np],   a_h[0], a_h[1], a_h[2], a_h[3], vl[0], vl[1]);
                MMA_BF16(co[2*np],   a_l[0], a_l[1], a_l[2], a_l[3], vh[0], vh[1]);
                MMA_BF16(co[2*np+1], a_h[0], a_h[1], a_h[2], a_h[3], vh[2], vh[3]);
                MMA_BF16(co[2*np+1], a_h[0], a_h[1], a_h[2], a_h[3], vl[2], vl[3]);
                MMA_BF16(co[2*np+1], a_l[0], a_l[1], a_l[2], a_l[3], vh[2], vh[3]);
            }
        }

        __syncthreads();
        if (kt + 2 < nkt) LOADKV(kt & 1, kt + 2);
    }

    // ---- finalize ----
    float inv0 = 1.f / lr[0], inv1 = 1.f / lr[1];
    int row0 = q0 + wm + g;
    size_t base0 = (size_t)(b*LL + row0) * DD + hh*DHD;
    size_t base1 = base0 + (size_t)8 * DD;
#pragma unroll
    for (int nb = 0; nb < 8; nb++) {
        int col = nb*8 + tq*2;
        uint32_t hh0, ll0, hh1, ll1;
        split2(co[nb][0]*inv0, co[nb][1]*inv0, hh0, ll0);
        split2(co[nb][2]*inv1, co[nb][3]*inv1, hh1, ll1);
        *(uint32_t*)&Oh[base0 + col] = hh0;
        *(uint32_t*)&Ol[base0 + col] = ll0;
        *(uint32_t*)&Oh[base1 + col] = hh1;
        *(uint32_t*)&Ol[base1 + col] = ll1;
    }
#undef LOADKV
}

// ---------------------------------------------------------------------------
// GEGLU: (hi,lo) in -> (hi,lo) out, 8 elems/thread vectorized
// ---------------------------------------------------------------------------
__global__ void geglu_kernel(const bf16* __restrict__ ph, const bf16* __restrict__ pl,
                             bf16* __restrict__ ah, bf16* __restrict__ al)
{
    long idx = (long)blockIdx.x * blockDim.x + threadIdx.x;
    long i8 = idx * 8;
    long row = i8 >> 11;                 // FFD = 2048
    long col = i8 & 2047;
    long iv = row * (2*FFD) + col;
    long ig = iv + FFD;

    uint4 hv = *(const uint4*)(ph + iv);
    uint4 lv = *(const uint4*)(pl + iv);
    uint4 hg = *(const uint4*)(ph + ig);
    uint4 lg = *(const uint4*)(pl + ig);

    const uint32_t* hvp = &hv.x; const uint32_t* lvp = &lv.x;
    const uint32_t* hgp = &hg.x; const uint32_t* lgp = &lg.x;
    uint4 oh4, ol4;
    uint32_t* ohp = &oh4.x; uint32_t* olp = &ol4.x;

#pragma unroll
    for (int j = 0; j < 4; j++) {
        __nv_bfloat162 hv2 = *(const __nv_bfloat162*)&hvp[j];
        __nv_bfloat162 lv2 = *(const __nv_bfloat162*)&lvp[j];
        __nv_bfloat162 hg2 = *(const __nv_bfloat162*)&hgp[j];
        __nv_bfloat162 lg2 = *(const __nv_bfloat162*)&lgp[j];
        float v0 = __bfloat162float(hv2.x) + __bfloat162float(lv2.x);
        float v1 = __bfloat162float(hv2.y) + __bfloat162float(lv2.y);
        float g0 = __bfloat162float(hg2.x) + __bfloat162float(lg2.x);
        float g1 = __bfloat162float(hg2.y) + __bfloat162float(lg2.y);
        float r0 = v0 * g0 * normcdff(g0);
        float r1 = v1 * g1 * normcdff(g1);
        split2(r0, r1, ohp[j], olp[j]);
    }
    *(uint4*)(ah + i8) = oh4;
    *(uint4*)(al + i8) = ol4;
}

// ---------------------------------------------------------------------------
extern "C" void kernel_launch(void* const* d_in, const int* in_sizes, int n_in,
                              void* d_out, int out_size)
{
    const float* x    = (const float*)d_in[0];
    const float* ctx  = (const float*)d_in[1];
    const float* ln1g = (const float*)d_in[2];
    const float* ln1b = (const float*)d_in[3];
    const float* ln2g = (const float*)d_in[4];
    const float* ln2b = (const float*)d_in[5];
    const float* ln3g = (const float*)d_in[6];
    const float* ln3b = (const float*)d_in[7];
    const float* a1wq = (const float*)d_in[8];
    const float* a1wk = (const float*)d_in[9];
    const float* a1wv = (const float*)d_in[10];
    const float* a1wo = (const float*)d_in[11];
    const float* a1bo = (const float*)d_in[12];
    const float* a2wq = (const float*)d_in[13];
    const float* a2wk = (const float*)d_in[14];
    const float* a2wv = (const float*)d_in[15];
    const float* a2wo = (const float*)d_in[16];
    const float* a2bo = (const float*)d_in[17];
    const float* ffw1 = (const float*)d_in[18];
    const float* ffb1 = (const float*)d_in[19];
    const float* ffw2 = (const float*)d_in[20];
    const float* ffb2 = (const float*)d_in[21];
    float* out = (float*)d_out;

    unsigned char* base = nullptr;
    cudaGetSymbolAddress((void**)&base, g_scratch);

    bf16* h_h   = (bf16*)(base + 0u*MB);
    bf16* h_l   = (bf16*)(base + 8u*MB);
    bf16* qkv_h = (bf16*)(base + 16u*MB);
    bf16* qkv_l = (bf16*)(base + 40u*MB);
    bf16* q_h   = (bf16*)(base + 64u*MB);
    bf16* q_l   = (bf16*)(base + 72u*MB);
    bf16* kv_h  = (bf16*)(base + 80u*MB);
    bf16* kv_l  = (bf16*)(base + 82u*MB);
    bf16* o_h   = (bf16*)(base + 84u*MB);
    bf16* o_l   = (bf16*)(base + 92u*MB);
    float* x1   = (float*)(base + 100u*MB);
    bf16* p_h   = (bf16*)(base + 116u*MB);
    bf16* p_l   = (bf16*)(base + 180u*MB);
    bf16* a_h   = (bf16*)(base + 244u*MB);
    bf16* a_l   = (bf16*)(base + 276u*MB);
    bf16* cx_h  = (bf16*)(base + 308u*MB);
    bf16* cx_l  = (bf16*)(base + 310u*MB);
    bf16* wcur  = (bf16*)(base + 312u*MB);

    bf16 *w1qkv_h, *w1qkv_l, *w1o_h, *w1o_l;
    bf16 *w2q_h, *w2q_l, *w2kv_h, *w2kv_l, *w2o_h, *w2o_l;
    bf16 *f1_h, *f1_l, *f2_h, *f2_l;
    {
        size_t cur = 0;
        auto al2 = [&](size_t n, bf16** hh, bf16** ll) {
            *hh = wcur + cur; cur += n; *ll = wcur + cur; cur += n;
        };
        al2(1536*512, &w1qkv_h, &w1qkv_l);
        al2(512*512,  &w1o_h, &w1o_l);
        al2(512*512,  &w2q_h, &w2q_l);
        al2(1024*768, &w2kv_h, &w2kv_l);
        al2(512*512,  &w2o_h, &w2o_l);
        al2(512*4096, &f1_h,  &f1_l);
        al2(2048*512, &f2_h,  &f2_l);
    }

    static bool attr_set = false;
    if (!attr_set) {
        cudaFuncSetAttribute(gemm_mma, cudaFuncAttributeMaxDynamicSharedMemorySize, GEMM_SMEM);
        cudaFuncSetAttribute(attn_mma, cudaFuncAttributeMaxDynamicSharedMemorySize, ATT_SMEM);
        attr_set = true;
    }

    dim3 tb(32, 8);
    tsplit_kernel<<<dim3(512/32, 512/32), tb>>>(a1wq, w1qkv_h,              w1qkv_l,              512, 512);
    tsplit_kernel<<<dim3(512/32, 512/32), tb>>>(a1wk, w1qkv_h + 512*512,    w1qkv_l + 512*512,    512, 512);
    tsplit_kernel<<<dim3(512/32, 512/32), tb>>>(a1wv, w1qkv_h + 2*512*512,  w1qkv_l + 2*512*512,  512, 512);
    tsplit_kernel<<<dim3(512/32, 512/32), tb>>>(a1wo, w1o_h, w1o_l, 512, 512);
    tsplit_kernel<<<dim3(512/32, 512/32), tb>>>(a2wq, w2q_h, w2q_l, 512, 512);
    tsplit_kernel<<<dim3(512/32, 768/32), tb>>>(a2wk, w2kv_h,            w2kv_l,            768, 512);
    tsplit_kernel<<<dim3(512/32, 768/32), tb>>>(a2wv, w2kv_h + 512*768,  w2kv_l + 512*768,  768, 512);
    tsplit_kernel<<<dim3(512/32, 512/32), tb>>>(a2wo, w2o_h, w2o_l, 512, 512);
    tsplit_kernel<<<dim3(4096/32, 512/32), tb>>>(ffw1, f1_h, f1_l, 512, 4096);
    tsplit_kernel<<<dim3(512/32, 2048/32), tb>>>(ffw2, f2_h, f2_l, 2048, 512);
    split_kernel<<<(CROWS*CDIM + 255)/256, 256>>>(ctx, cx_h, cx_l, CROWS*CDIM);

    dim3 gQKV(1536/128, ROWS/128);
    dim3 g512(512/128, ROWS/128);
    dim3 gKV(1024/128, (CROWS+127)/128);
    dim3 gFF1(4096/128, ROWS/128);
    dim3 gattn(LL/128, HH, BB);

    // --- self attention block ---
    ln_kernel<<<ROWS, 128>>>(x, ln1g, ln1b, h_h, h_l);
    gemm_mma<<<gQKV, 256, GEMM_SMEM>>>(h_h, h_l, w1qkv_h, w1qkv_l, nullptr, nullptr, nullptr, qkv_h, qkv_l, ROWS, 1536, 512);
    attn_mma<<<gattn, 256, ATT_SMEM>>>(qkv_h, qkv_l, qkv_h + 512, qkv_l + 512, qkv_h + 1024, qkv_l + 1024,
                                       o_h, o_l, LL, LL, 1536, 1536);
    gemm_mma<<<g512, 256, GEMM_SMEM>>>(o_h, o_l, w1o_h, w1o_l, a1bo, x, x1, nullptr, nullptr, ROWS, 512, 512);

    // --- cross attention block ---
    ln_kernel<<<ROWS, 128>>>(x1, ln2g, ln2b, h_h, h_l);
    gemm_mma<<<g512, 256, GEMM_SMEM>>>(h_h, h_l, w2q_h, w2q_l, nullptr, nullptr, nullptr, q_h, q_l, ROWS, 512, 512);
    gemm_mma<<<gKV, 256, GEMM_SMEM>>>(cx_h, cx_l, w2kv_h, w2kv_l, nullptr, nullptr, nullptr, kv_h, kv_l, CROWS, 1024, 768);
    attn_mma<<<gattn, 256, ATT_SMEM>>>(q_h, q_l, kv_h, kv_l, kv_h + 512, kv_l + 512,
                                       o_h, o_l, SS, SS, 512, 1024);
    gemm_mma<<<g512, 256, GEMM_SMEM>>>(o_h, o_l, w2o_h, w2o_l, a2bo, x1, x1, nullptr, nullptr, ROWS, 512, 512);

    // --- GEGLU feed-forward ---
    ln_kernel<<<ROWS, 128>>>(x1, ln3g, ln3b, h_h, h_l);
    gemm_mma<<<gFF1, 256, GEMM_SMEM>>>(h_h, h_l, f1_h, f1_l, ffb1, nullptr, nullptr, p_h, p_l, ROWS, 4096, 512);
    geglu_kernel<<<(ROWS * FFD) / (8*256), 256>>>(p_h, p_l, a_h, a_l);
    gemm_mma<<<g512, 256, GEMM_SMEM>>>(a_h, a_l, f2_h, f2_l, ffb2, x1, out, nullptr, nullptr, ROWS, 512, FFD);
}

// round 7
// speedup vs baseline: 4.5125x; 1.0059x over previous
#include <cuda_runtime.h>
#include <cuda_bf16.h>
#include <math.h>
#include <stdint.h>

typedef __nv_bfloat16 bf16;

#define BB   8
#define LL   1024
#define SS   77
#define DD   512
#define HH   8
#define DHD  64
#define CDIM 768
#define FFD  2048
#define ROWS  (BB*LL)   /* 8192 */
#define CROWS (BB*SS)   /* 616  */

#define MB (1024u*1024u)
__device__ __align__(256) unsigned char g_scratch[448u*MB];

extern __shared__ __align__(16) unsigned char dynsmem[];

// ---------------------------------------------------------------------------
// helpers
// ---------------------------------------------------------------------------
__device__ __forceinline__ uint32_t pack2(bf16 a, bf16 b) {
    __nv_bfloat162 t(a, b);
    return *(uint32_t*)&t;
}
__device__ __forceinline__ void split2(float x, float y, uint32_t& h, uint32_t& l) {
    bf16 hx = __float2bfloat16(x), hy = __float2bfloat16(y);
    bf16 lx = __float2bfloat16(x - __bfloat162float(hx));
    bf16 ly = __float2bfloat16(y - __bfloat162float(hy));
    h = pack2(hx, hy);
    l = pack2(lx, ly);
}
__device__ __forceinline__ void cp16(uint32_t dst, const void* src, int srcsize) {
    asm volatile("cp.async.cg.shared.global [%0], [%1], 16, %2;\n"
                 :: "r"(dst), "l"(src), "r"(srcsize));
}
__device__ __forceinline__ void cp_commit() {
    asm volatile("cp.async.commit_group;\n" ::: "memory");
}
__device__ __forceinline__ void cp_wait1() {
    asm volatile("cp.async.wait_group 1;\n" ::: "memory");
}
__device__ __forceinline__ void cp_wait0() {
    asm volatile("cp.async.wait_group 0;\n" ::: "memory");
}

#define LDMX4(r0, r1, r2, r3, addr)                                            \
    asm volatile("ldmatrix.sync.aligned.m8n8.x4.shared.b16 {%0,%1,%2,%3}, [%4];"\
                 : "=r"(r0), "=r"(r1), "=r"(r2), "=r"(r3) : "r"(addr))

#define LDMT4(r0, r1, r2, r3, addr)                                            \
    asm volatile("ldmatrix.sync.aligned.m8n8.x4.trans.shared.b16 {%0,%1,%2,%3}, [%4];"\
                 : "=r"(r0), "=r"(r1), "=r"(r2), "=r"(r3) : "r"(addr))

#define MMA_BF16(d, a0, a1, a2, a3, b0, b1)                                      \
    asm volatile("mma.sync.aligned.m16n8k16.row.col.f32.bf16.bf16.f32 "          \
                 "{%0,%1,%2,%3},{%4,%5,%6,%7},{%8,%9},{%0,%1,%2,%3};"            \
                 : "+f"(d[0]), "+f"(d[1]), "+f"(d[2]), "+f"(d[3])                 \
                 : "r"(a0), "r"(a1), "r"(a2), "r"(a3), "r"(b0), "r"(b1))

// ---------------------------------------------------------------------------
// LayerNorm: fp32 in -> (hi, lo) bf16 out  (vectorized)
// ---------------------------------------------------------------------------
__global__ void ln_kernel(const float* __restrict__ x, const float* __restrict__ gamma,
                          const float* __restrict__ beta,
                          bf16* __restrict__ oh, bf16* __restrict__ ol)
{
    int row = blockIdx.x;
    int t = threadIdx.x;
    float4 v = ((const float4*)(x + (long)row * DD))[t];

    float s = v.x + v.y + v.z + v.w;
    __shared__ float red[4];
    __shared__ float red2[4];
#pragma unroll
    for (int off = 16; off; off >>= 1) s += __shfl_xor_sync(0xffffffffu, s, off);
    if ((t & 31) == 0) red[t >> 5] = s;
    __syncthreads();
    float mean = (red[0] + red[1] + red[2] + red[3]) * (1.f/512.f);

    float dx = v.x - mean, dy = v.y - mean, dz = v.z - mean, dw = v.w - mean;
    float sq = dx*dx + dy*dy + dz*dz + dw*dw;
#pragma unroll
    for (int off = 16; off; off >>= 1) sq += __shfl_xor_sync(0xffffffffu, sq, off);
    if ((t & 31) == 0) red2[t >> 5] = sq;
    __syncthreads();
    float var = (red2[0] + red2[1] + red2[2] + red2[3]) * (1.f/512.f);
    float rstd = rsqrtf(var + 1e-5f);

    float4 g4 = ((const float4*)gamma)[t];
    float4 b4 = ((const float4*)beta)[t];
    float y0 = dx * rstd * g4.x + b4.x;
    float y1 = dy * rstd * g4.y + b4.y;
    float y2 = dz * rstd * g4.z + b4.z;
    float y3 = dw * rstd * g4.w + b4.w;
    uint32_t h01, l01, h23, l23;
    split2(y0, y1, h01, l01);
    split2(y2, y3, h23, l23);
    uint2 hv = {h01, h23}, lv = {l01, l23};
    ((uint2*)(oh + (long)row * DD))[t] = hv;
    ((uint2*)(ol + (long)row * DD))[t] = lv;
}

// ---------------------------------------------------------------------------
// Batched conversion kernel: all weight transpose-splits + ctx split, 1 launch.
// mode 0: W[K,N] -> Th/Tl [N,K] transpose+split
// mode 1: same but dest row interleaved for GEGLU (val j -> 2j, gate j -> 2j+1)
// mode 2: plain elementwise split, W[K,N] -> Th/Tl [K,N] (row-guarded)
// ---------------------------------------------------------------------------
struct ConvJob {
    const float* W;
    bf16* Th;
    bf16* Tl;
    int K, N, tileStart, tilesPerRow, mode;
};
struct ConvArgs { ConvJob j[11]; };

__global__ void conv_kernel(ConvArgs a)
{
    int bid = blockIdx.x;
    int ji = 0;
#pragma unroll
    for (int i = 1; i < 11; i++)
        if (bid >= a.j[i].tileStart) ji = i;
    ConvJob jb = a.j[ji];
    int t = bid - jb.tileStart;
    int n0 = (t % jb.tilesPerRow) * 32;
    int k0 = (t / jb.tilesPerRow) * 32;
    int x = threadIdx.x, y = threadIdx.y;   // 32 x 8

    if (jb.mode == 2) {
#pragma unroll
        for (int i = 0; i < 32; i += 8) {
            int r = k0 + y + i;
            if (r < jb.K) {
                size_t o = (size_t)r * jb.N + n0 + x;
                float v = jb.W[o];
                bf16 h = __float2bfloat16(v);
                jb.Th[o] = h;
                jb.Tl[o] = __float2bfloat16(v - __bfloat162float(h));
            }
        }
        return;
    }

    __shared__ float tl[32][33];
#pragma unroll
    for (int i = 0; i < 32; i += 8)
        tl[y + i][x] = jb.W[(size_t)(k0 + y + i) * jb.N + n0 + x];
    __syncthreads();
#pragma unroll
    for (int i = 0; i < 32; i += 8) {
        float v = tl[x][y + i];
        bf16 h = __float2bfloat16(v);
        bf16 l = __float2bfloat16(v - __bfloat162float(h));
        int n = n0 + y + i;
        int dr = (jb.mode == 1) ? ((n < FFD) ? 2*n : 2*(n - FFD) + 1) : n;
        size_t o = (size_t)dr * jb.K + k0 + x;
        jb.Th[o] = h;
        jb.Tl[o] = l;
    }
}

// ---------------------------------------------------------------------------
// bf16-split tensor-core GEMM, ldmatrix edition.
// Epilogue modes: geglu=1 -> fused GEGLU (interleaved val/gate cols, out N/2);
//                 Ch!=null -> (hi,lo)+bias; else fp32 +bias +res.
// ---------------------------------------------------------------------------
#define BKC 32
#define LDA 40
#define ST_ELE (4*128*LDA)
#define S_AH 0
#define S_AL (128*LDA)
#define S_BH (2*128*LDA)
#define S_BL (3*128*LDA)
#define NSTAGE 2
#define GEMM_SMEM (NSTAGE * ST_ELE * 2)

__global__ void __launch_bounds__(256)
gemm_mma(const bf16* __restrict__ Ah, const bf16* __restrict__ Al,
         const bf16* __restrict__ Bh, const bf16* __restrict__ Bl,
         const float* __restrict__ bias, const float* __restrict__ res,
         float* __restrict__ C, bf16* __restrict__ Ch, bf16* __restrict__ Cl,
         int M, int N, int K, int geglu)
{
    bf16* sm = (bf16*)dynsmem;
    uint32_t smb = (uint32_t)__cvta_generic_to_shared(sm);

    int tid = threadIdx.x;
    int m0 = blockIdx.y * 128, n0 = blockIdx.x * 128;
    int wid = tid >> 5, lane = tid & 31;
    int wm = (wid & 1) * 64, wn = (wid >> 1) * 32;
    int g = lane >> 2, tq = lane & 3;

    float c[4][4][4];
#pragma unroll
    for (int i = 0; i < 4; i++)
#pragma unroll
        for (int j = 0; j < 4; j++)
#pragma unroll
            for (int r = 0; r < 4; r++) c[i][j][r] = 0.f;

    uint32_t aoff = (uint32_t)((wm + (lane & 15)) * LDA + (lane >> 4) * 8) * 2;
    uint32_t boff = (uint32_t)((wn + ((lane >> 4) & 1) * 8 + (lane & 7)) * LDA
                               + ((lane >> 3) & 1) * 8) * 2;

    int r0 = tid >> 2, kc = tid & 3;
    int mA0 = m0 + r0, mA1 = m0 + r0 + 64;
    int szA0 = (mA0 < M) ? 16 : 0;
    int szA1 = (mA1 < M) ? 16 : 0;
    const bf16* pAh0 = Ah + (size_t)min(mA0, M-1) * K + kc*8;
    const bf16* pAh1 = Ah + (size_t)min(mA1, M-1) * K + kc*8;
    const bf16* pAl0 = Al + (size_t)min(mA0, M-1) * K + kc*8;
    const bf16* pAl1 = Al + (size_t)min(mA1, M-1) * K + kc*8;
    const bf16* pBh0 = Bh + (size_t)(n0 + r0) * K + kc*8;
    const bf16* pBh1 = Bh + (size_t)(n0 + r0 + 64) * K + kc*8;
    const bf16* pBl0 = Bl + (size_t)(n0 + r0) * K + kc*8;
    const bf16* pBl1 = Bl + (size_t)(n0 + r0 + 64) * K + kc*8;
    uint32_t dA0 = smb + (uint32_t)(S_AH + r0*LDA + kc*8) * 2;
    uint32_t dA1 = smb + (uint32_t)(S_AH + (r0+64)*LDA + kc*8) * 2;
    uint32_t dL0 = smb + (uint32_t)(S_AL + r0*LDA + kc*8) * 2;
    uint32_t dL1 = smb + (uint32_t)(S_AL + (r0+64)*LDA + kc*8) * 2;
    uint32_t dB0 = smb + (uint32_t)(S_BH + r0*LDA + kc*8) * 2;
    uint32_t dB1 = smb + (uint32_t)(S_BH + (r0+64)*LDA + kc*8) * 2;
    uint32_t dC0 = smb + (uint32_t)(S_BL + r0*LDA + kc*8) * 2;
    uint32_t dC1 = smb + (uint32_t)(S_BL + (r0+64)*LDA + kc*8) * 2;

#define LOAD_STAGE(s, k0v)                                                     \
    do {                                                                       \
        uint32_t so = (uint32_t)(s) * (ST_ELE * 2);                            \
        cp16(dA0 + so, pAh0 + (k0v), szA0);                                    \
        cp16(dA1 + so, pAh1 + (k0v), szA1);                                    \
        cp16(dL0 + so, pAl0 + (k0v), szA0);                                    \
        cp16(dL1 + so, pAl1 + (k0v), szA1);                                    \
        cp16(dB0 + so, pBh0 + (k0v), 16);                                      \
        cp16(dB1 + so, pBh1 + (k0v), 16);                                      \
        cp16(dC0 + so, pBl0 + (k0v), 16);                                      \
        cp16(dC1 + so, pBl1 + (k0v), 16);                                      \
        cp_commit();                                                           \
    } while (0)

    int nk = K / BKC;
    LOAD_STAGE(0, 0);
    LOAD_STAGE(1, BKC);

    for (int kt = 0; kt < nk; kt++) {
        if (kt + 2 <= nk) cp_wait1(); else cp_wait0();
        __syncthreads();
        uint32_t sbase = smb + (uint32_t)(kt & 1) * (ST_ELE * 2);

#pragma unroll
        for (int kk = 0; kk < BKC; kk += 16) {
            uint32_t ah[4][4], al[4][4], bh[4][2], bl[4][2];
#pragma unroll
            for (int mb = 0; mb < 4; mb++) {
                uint32_t ra = sbase + aoff + (uint32_t)(mb*16*LDA + kk) * 2;
                LDMX4(ah[mb][0], ah[mb][1], ah[mb][2], ah[mb][3], ra + S_AH*2);
                LDMX4(al[mb][0], al[mb][1], al[mb][2], al[mb][3], ra + S_AL*2);
            }
#pragma unroll
            for (int p = 0; p < 2; p++) {
                uint32_t rb = sbase + boff + (uint32_t)(p*16*LDA + kk) * 2;
                LDMX4(bh[2*p][0], bh[2*p][1], bh[2*p+1][0], bh[2*p+1][1], rb + S_BH*2);
                LDMX4(bl[2*p][0], bl[2*p][1], bl[2*p+1][0], bl[2*p+1][1], rb + S_BL*2);
            }
#pragma unroll
            for (int mb = 0; mb < 4; mb++)
#pragma unroll
                for (int nb = 0; nb < 4; nb++) {
                    MMA_BF16(c[mb][nb], ah[mb][0], ah[mb][1], ah[mb][2], ah[mb][3], bh[nb][0], bh[nb][1]);
                    MMA_BF16(c[mb][nb], ah[mb][0], ah[mb][1], ah[mb][2], ah[mb][3], bl[nb][0], bl[nb][1]);
                    MMA_BF16(c[mb][nb], al[mb][0], al[mb][1], al[mb][2], al[mb][3], bh[nb][0], bh[nb][1]);
                }
        }
        __syncthreads();
        if (kt + 2 < nk) LOAD_STAGE(kt & 1, (kt + 2) * BKC);
    }

    // epilogue
    if (geglu) {
        int No = N >> 1;  // output width (2048)
#pragma unroll
        for (int mb = 0; mb < 4; mb++) {
#pragma unroll
            for (int nb = 0; nb < 4; nb++) {
                int m = m0 + wm + mb*16 + g;
                int n = n0 + wn + nb*8 + tq*2;   // even (val), n+1 = gate
                int j = n >> 1;
                float bv = bias[j], bg = bias[FFD + j];
#pragma unroll
                for (int half = 0; half < 2; half++) {
                    int mm = m + half*8;
                    if (mm < M) {
                        float val  = c[mb][nb][2*half]   + bv;
                        float gate = c[mb][nb][2*half+1] + bg;
                        float rr = val * gate * normcdff(gate);
                        bf16 hh = __float2bfloat16(rr);
                        size_t idx = (size_t)mm * No + j;
                        Ch[idx] = hh;
                        Cl[idx] = __float2bfloat16(rr - __bfloat162float(hh));
                    }
                }
            }
        }
        return;
    }
#pragma unroll
    for (int mb = 0; mb < 4; mb++) {
#pragma unroll
        for (int nb = 0; nb < 4; nb++) {
            int m = m0 + wm + mb*16 + g;
            int n = n0 + wn + nb*8 + tq*2;
            float b0 = bias ? bias[n]   : 0.f;
            float b1 = bias ? bias[n+1] : 0.f;
            if (Ch) {
                if (m < M) {
                    size_t idx = (size_t)m * N + n;
                    uint32_t hh, ll;
                    split2(c[mb][nb][0] + b0, c[mb][nb][1] + b1, hh, ll);
                    *(uint32_t*)&Ch[idx] = hh;
                    *(uint32_t*)&Cl[idx] = ll;
                }
                if (m + 8 < M) {
                    size_t idx = (size_t)(m+8) * N + n;
                    uint32_t hh, ll;
                    split2(c[mb][nb][2] + b0, c[mb][nb][3] + b1, hh, ll);
                    *(uint32_t*)&Ch[idx] = hh;
                    *(uint32_t*)&Cl[idx] = ll;
                }
            } else {
                if (m < M) {
                    size_t idx = (size_t)m * N + n;
                    float v0 = c[mb][nb][0] + b0;
                    float v1 = c[mb][nb][1] + b1;
                    if (res) { v0 += res[idx]; v1 += res[idx+1]; }
                    C[idx] = v0; C[idx+1] = v1;
                }
                if (m + 8 < M) {
                    size_t idx = (size_t)(m+8) * N + n;
                    float v0 = c[mb][nb][2] + b0;
                    float v1 = c[mb][nb][3] + b1;
                    if (res) { v0 += res[idx]; v1 += res[idx+1]; }
                    C[idx] = v0; C[idx+1] = v1;
                }
            }
        }
    }
#undef LOAD_STAGE
}

// ---------------------------------------------------------------------------
// Flash attention: 256 threads, 128 q rows/block, cp.async double-buffered
// K/V, ldmatrix fragments, V via ldmatrix.trans. (unchanged from round 6)
// ---------------------------------------------------------------------------
#define ATT_LD 72
#define AQ_H 0
#define AQ_L (128*ATT_LD)
#define ASTG (2*128*ATT_LD)
#define STG_SZ (4*64*ATT_LD)
#define KH_O 0
#define KL_O (64*ATT_LD)
#define VH_O (2*64*ATT_LD)
#define VL_O (3*64*ATT_LD)
#define ATT_SMEM ((ASTG + 2*STG_SZ)*2)

__global__ void __launch_bounds__(256, 2)
attn_mma(const bf16* __restrict__ Qh, const bf16* __restrict__ Ql,
         const bf16* __restrict__ Kh, const bf16* __restrict__ Kl,
         const bf16* __restrict__ Vh, const bf16* __restrict__ Vl,
         bf16* __restrict__ Oh, bf16* __restrict__ Ol,
         int Lk, int kvL, int qStride, int kvStride)
{
    bf16* sm = (bf16*)dynsmem;
    uint32_t smb = (uint32_t)__cvta_generic_to_shared(sm);
    int b = blockIdx.z, hh = blockIdx.y, q0 = blockIdx.x * 128;
    int tid = threadIdx.x;
    int wid = tid >> 5, lane = tid & 31;
    int g = lane >> 2, tq = lane & 3;
    int wm = wid * 16;

    {
        __nv_bfloat162 sc = __floats2bfloat162_rn(0.125f, 0.125f);
#pragma unroll
        for (int u = 0; u < 16; u++) {
            int i = tid + u*256;
            int row = i >> 5, dp = (i & 31) * 2;
            size_t gq = (size_t)(b*LL + q0 + row) * qStride + hh*DHD + dp;
            __nv_bfloat162 th = __hmul2(*(const __nv_bfloat162*)(Qh + gq), sc);
            __nv_bfloat162 tl = __hmul2(*(const __nv_bfloat162*)(Ql + gq), sc);
            *(__nv_bfloat162*)&sm[AQ_H + row*ATT_LD + dp] = th;
            *(__nv_bfloat162*)&sm[AQ_L + row*ATT_LD + dp] = tl;
        }
    }

#define LOADKV(s, ktile)                                                      \
    do {                                                                      \
        int kb = (ktile) * 64;                                                \
        uint32_t so = (uint32_t)(ASTG + (s)*STG_SZ);                          \
        _Pragma("unroll")                                                     \
        for (int u = 0; u < 2; u++) {                                         \
            int rem = tid + u*256;                                            \
            int row = rem >> 3, ch = rem & 7;                                 \
            int krow = kb + row;                                              \
            int szk = (krow < Lk) ? 16 : 0;                                   \
            size_t gix = (size_t)(b*kvL + (szk ? krow : 0)) * kvStride        \
                         + hh*DHD + ch*8;                                     \
            uint32_t da = smb + (so + row*ATT_LD + ch*8) * 2;                 \
            cp16(da,           Kh + gix, szk);                                \
            cp16(da + KL_O*2,  Kl + gix, szk);                                \
            cp16(da + VH_O*2,  Vh + gix, szk);                                \
            cp16(da + VL_O*2,  Vl + gix, szk);                                \
        }                                                                     \
        cp_commit();                                                          \
    } while (0)

    int nkt = (Lk + 63) >> 6;
    LOADKV(0, 0);
    if (nkt > 1) LOADKV(1, 1);

    float mr[2] = {-1e30f, -1e30f};
    float lr[2] = {0.f, 0.f};
    float co[8][4];
#pragma unroll
    for (int nb = 0; nb < 8; nb++)
#pragma unroll
        for (int r = 0; r < 4; r++) co[nb][r] = 0.f;

    for (int kt = 0; kt < nkt; kt++) {
        if (kt + 2 <= nkt && nkt > 1) cp_wait1(); else cp_wait0();
        __syncthreads();
        uint32_t ss = (uint32_t)(ASTG + (kt & 1) * STG_SZ);

        float s[8][4];
#pragma unroll
        for (int nb = 0; nb < 8; nb++)
#pragma unroll
            for (int r = 0; r < 4; r++) s[nb][r] = 0.f;

#pragma unroll
        for (int ks = 0; ks < 4; ks++) {
            uint32_t qh[4], ql[4];
            uint32_t qa = smb + (uint32_t)((wm + (lane & 15))*ATT_LD
                                           + ks*16 + (lane >> 4)*8) * 2;
            LDMX4(qh[0], qh[1], qh[2], qh[3], qa + AQ_H*2);
            LDMX4(ql[0], ql[1], ql[2], ql[3], qa + AQ_L*2);
#pragma unroll
            for (int kp = 0; kp < 4; kp++) {
                uint32_t kh[4], kl[4];
                uint32_t ka = smb + (ss + (uint32_t)((kp*16 + ((lane>>4)&1)*8 + (lane&7))*ATT_LD
                                                     + ks*16 + ((lane>>3)&1)*8)) * 2;
                LDMX4(kh[0], kh[1], kh[2], kh[3], ka + KH_O*2);
                LDMX4(kl[0], kl[1], kl[2], kl[3], ka + KL_O*2);
                MMA_BF16(s[2*kp],   qh[0], qh[1], qh[2], qh[3], kh[0], kh[1]);
                MMA_BF16(s[2*kp],   qh[0], qh[1], qh[2], qh[3], kl[0], kl[1]);
                MMA_BF16(s[2*kp],   ql[0], ql[1], ql[2], ql[3], kh[0], kh[1]);
                MMA_BF16(s[2*kp+1], qh[0], qh[1], qh[2], qh[3], kh[2], kh[3]);
                MMA_BF16(s[2*kp+1], qh[0], qh[1], qh[2], qh[3], kl[2], kl[3]);
                MMA_BF16(s[2*kp+1], ql[0], ql[1], ql[2], ql[3], kh[2], kh[3]);
            }
        }

        if ((kt + 1) * 64 > Lk) {
#pragma unroll
            for (int nb = 0; nb < 8; nb++) {
                int key = kt*64 + nb*8 + tq*2;
                if (key     >= Lk) { s[nb][0] = -1e30f; s[nb][2] = -1e30f; }
                if (key + 1 >= Lk) { s[nb][1] = -1e30f; s[nb][3] = -1e30f; }
            }
        }

#pragma unroll
        for (int r = 0; r < 2; r++) {
            int i0 = 2*r, i1 = 2*r + 1;
            float tm = -1e30f;
#pragma unroll
            for (int nb = 0; nb < 8; nb++)
                tm = fmaxf(tm, fmaxf(s[nb][i0], s[nb][i1]));
            tm = fmaxf(tm, __shfl_xor_sync(0xffffffffu, tm, 1));
            tm = fmaxf(tm, __shfl_xor_sync(0xffffffffu, tm, 2));
            float mnew = fmaxf(mr[r], tm);
            float alpha = __expf(mr[r] - mnew);
            mr[r] = mnew;
            float sum = 0.f;
#pragma unroll
            for (int nb = 0; nb < 8; nb++) {
                s[nb][i0] = __expf(s[nb][i0] - mnew); sum += s[nb][i0];
                s[nb][i1] = __expf(s[nb][i1] - mnew); sum += s[nb][i1];
            }
            sum += __shfl_xor_sync(0xffffffffu, sum, 1);
            sum += __shfl_xor_sync(0xffffffffu, sum, 2);
            lr[r] = lr[r] * alpha + sum;
#pragma unroll
            for (int nb = 0; nb < 8; nb++) { co[nb][i0] *= alpha; co[nb][i1] *= alpha; }
        }

#pragma unroll
        for (int ks = 0; ks < 4; ks++) {
            uint32_t a_h[4], a_l[4];
            split2(s[2*ks  ][0], s[2*ks  ][1], a_h[0], a_l[0]);
            split2(s[2*ks  ][2], s[2*ks  ][3], a_h[1], a_l[1]);
            split2(s[2*ks+1][0], s[2*ks+1][1], a_h[2], a_l[2]);
            split2(s[2*ks+1][2], s[2*ks+1][3], a_h[3], a_l[3]);
#pragma unroll
            for (int np = 0; np < 4; np++) {
                uint32_t vh[4], vl[4];
                uint32_t va = smb + (ss + (uint32_t)(VH_O + (ks*16 + (lane & 15))*ATT_LD
                                                     + np*16 + ((lane >> 4) << 3))) * 2;
                LDMT4(vh[0], vh[1], vh[2], vh[3], va);
                LDMT4(vl[0], vl[1], vl[2], vl[3], va + (VL_O - VH_O)*2);
                MMA_BF16(co[2*np],   a_h[0], a_h[1], a_h[2], a_h[3], vh[0], vh[1]);
                MMA_BF16(co[2*np],   a_h[0], a_h[1], a_h[2], a_h[3], vl[0], vl[1]);
                MMA_BF16(co[2*np],   a_l[0], a_l[1], a_l[2], a_l[3], vh[0], vh[1]);
                MMA_BF16(co[2*np+1], a_h[0], a_h[1], a_h[2], a_h[3], vh[2], vh[3]);
                MMA_BF16(co[2*np+1], a_h[0], a_h[1], a_h[2], a_h[3], vl[2], vl[3]);
                MMA_BF16(co[2*np+1], a_l[0], a_l[1], a_l[2], a_l[3], vh[2], vh[3]);
            }
        }

        __syncthreads();
        if (kt + 2 < nkt) LOADKV(kt & 1, kt + 2);
    }

    float inv0 = 1.f / lr[0], inv1 = 1.f / lr[1];
    int row0 = q0 + wm + g;
    size_t base0 = (size_t)(b*LL + row0) * DD + hh*DHD;
    size_t base1 = base0 + (size_t)8 * DD;
#pragma unroll
    for (int nb = 0; nb < 8; nb++) {
        int col = nb*8 + tq*2;
        uint32_t hh0, ll0, hh1, ll1;
        split2(co[nb][0]*inv0, co[nb][1]*inv0, hh0, ll0);
        split2(co[nb][2]*inv1, co[nb][3]*inv1, hh1, ll1);
        *(uint32_t*)&Oh[base0 + col] = hh0;
        *(uint32_t*)&Ol[base0 + col] = ll0;
        *(uint32_t*)&Oh[base1 + col] = hh1;
        *(uint32_t*)&Ol[base1 + col] = ll1;
    }
#undef LOADKV
}

// ---------------------------------------------------------------------------
extern "C" void kernel_launch(void* const* d_in, const int* in_sizes, int n_in,
                              void* d_out, int out_size)
{
    const float* x    = (const float*)d_in[0];
    const float* ctx  = (const float*)d_in[1];
    const float* ln1g = (const float*)d_in[2];
    const float* ln1b = (const float*)d_in[3];
    const float* ln2g = (const float*)d_in[4];
    const float* ln2b = (const float*)d_in[5];
    const float* ln3g = (const float*)d_in[6];
    const float* ln3b = (const float*)d_in[7];
    const float* a1wq = (const float*)d_in[8];
    const float* a1wk = (const float*)d_in[9];
    const float* a1wv = (const float*)d_in[10];
    const float* a1wo = (const float*)d_in[11];
    const float* a1bo = (const float*)d_in[12];
    const float* a2wq = (const float*)d_in[13];
    const float* a2wk = (const float*)d_in[14];
    const float* a2wv = (const float*)d_in[15];
    const float* a2wo = (const float*)d_in[16];
    const float* a2bo = (const float*)d_in[17];
    const float* ffw1 = (const float*)d_in[18];
    const float* ffb1 = (const float*)d_in[19];
    const float* ffw2 = (const float*)d_in[20];
    const float* ffb2 = (const float*)d_in[21];
    float* out = (float*)d_out;

    unsigned char* base = nullptr;
    cudaGetSymbolAddress((void**)&base, g_scratch);

    bf16* h_h   = (bf16*)(base + 0u*MB);
    bf16* h_l   = (bf16*)(base + 8u*MB);
    bf16* qkv_h = (bf16*)(base + 16u*MB);
    bf16* qkv_l = (bf16*)(base + 40u*MB);
    bf16* q_h   = (bf16*)(base + 64u*MB);
    bf16* q_l   = (bf16*)(base + 72u*MB);
    bf16* kv_h  = (bf16*)(base + 80u*MB);
    bf16* kv_l  = (bf16*)(base + 82u*MB);
    bf16* o_h   = (bf16*)(base + 84u*MB);
    bf16* o_l   = (bf16*)(base + 92u*MB);
    float* x1   = (float*)(base + 100u*MB);
    bf16* a_h   = (bf16*)(base + 116u*MB);
    bf16* a_l   = (bf16*)(base + 148u*MB);
    bf16* cx_h  = (bf16*)(base + 180u*MB);
    bf16* cx_l  = (bf16*)(base + 182u*MB);
    bf16* wcur  = (bf16*)(base + 184u*MB);

    bf16 *w1qkv_h, *w1qkv_l, *w1o_h, *w1o_l;
    bf16 *w2q_h, *w2q_l, *w2kv_h, *w2kv_l, *w2o_h, *w2o_l;
    bf16 *f1_h, *f1_l, *f2_h, *f2_l;
    {
        size_t cur = 0;
        auto al2 = [&](size_t n, bf16** hh, bf16** ll) {
            *hh = wcur + cur; cur += n; *ll = wcur + cur; cur += n;
        };
        al2(1536*512, &w1qkv_h, &w1qkv_l);
        al2(512*512,  &w1o_h, &w1o_l);
        al2(512*512,  &w2q_h, &w2q_l);
        al2(1024*768, &w2kv_h, &w2kv_l);
        al2(512*512,  &w2o_h, &w2o_l);
        al2(512*4096, &f1_h,  &f1_l);
        al2(2048*512, &f2_h,  &f2_l);
    }

    static bool attr_set = false;
    if (!attr_set) {
        cudaFuncSetAttribute(gemm_mma, cudaFuncAttributeMaxDynamicSharedMemorySize, GEMM_SMEM);
        cudaFuncSetAttribute(attn_mma, cudaFuncAttributeMaxDynamicSharedMemorySize, ATT_SMEM);
        attr_set = true;
    }

    // ---- single batched conversion launch ----
    {
        ConvArgs ca;
        int ts = 0;
        auto J = [&](int i, const float* W, bf16* Th, bf16* Tl, int K, int N, int mode) {
            int tpr = N / 32;
            int rows = (mode == 2) ? (K + 31) / 32 : K / 32;
            ca.j[i] = {W, Th, Tl, K, N, ts, tpr, mode};
            ts += rows * tpr;
        };
        J(0, a1wq, w1qkv_h,             w1qkv_l,             512, 512, 0);
        J(1, a1wk, w1qkv_h + 512*512,   w1qkv_l + 512*512,   512, 512, 0);
        J(2, a1wv, w1qkv_h + 2*512*512, w1qkv_l + 2*512*512, 512, 512, 0);
        J(3, a1wo, w1o_h, w1o_l, 512, 512, 0);
        J(4, a2wq, w2q_h, w2q_l, 512, 512, 0);
        J(5, a2wk, w2kv_h,           w2kv_l,           768, 512, 0);
        J(6, a2wv, w2kv_h + 512*768, w2kv_l + 512*768, 768, 512, 0);
        J(7, a2wo, w2o_h, w2o_l, 512, 512, 0);
        J(8, ffw1, f1_h, f1_l, 512, 4096, 1);
        J(9, ffw2, f2_h, f2_l, 2048, 512, 0);
        J(10, ctx, cx_h, cx_l, CROWS, CDIM, 2);
        conv_kernel<<<ts, dim3(32, 8)>>>(ca);
    }

    dim3 gQKV(1536/128, ROWS/128);
    dim3 g512(512/128, ROWS/128);
    dim3 gKV(1024/128, (CROWS+127)/128);
    dim3 gFF1(4096/128, ROWS/128);
    dim3 gattn(LL/128, HH, BB);

    // --- self attention block ---
    ln_kernel<<<ROWS, 128>>>(x, ln1g, ln1b, h_h, h_l);
    gemm_mma<<<gQKV, 256, GEMM_SMEM>>>(h_h, h_l, w1qkv_h, w1qkv_l, nullptr, nullptr, nullptr, qkv_h, qkv_l, ROWS, 1536, 512, 0);
    attn_mma<<<gattn, 256, ATT_SMEM>>>(qkv_h, qkv_l, qkv_h + 512, qkv_l + 512, qkv_h + 1024, qkv_l + 1024,
                                       o_h, o_l, LL, LL, 1536, 1536);
    gemm_mma<<<g512, 256, GEMM_SMEM>>>(o_h, o_l, w1o_h, w1o_l, a1bo, x, x1, nullptr, nullptr, ROWS, 512, 512, 0);

    // --- cross attention block ---
    ln_kernel<<<ROWS, 128>>>(x1, ln2g, ln2b, h_h, h_l);
    gemm_mma<<<g512, 256, GEMM_SMEM>>>(h_h, h_l, w2q_h, w2q_l, nullptr, nullptr, nullptr, q_h, q_l, ROWS, 512, 512, 0);
    gemm_mma<<<gKV, 256, GEMM_SMEM>>>(cx_h, cx_l, w2kv_h, w2kv_l, nullptr, nullptr, nullptr, kv_h, kv_l, CROWS, 1024, 768, 0);
    attn_mma<<<gattn, 256, ATT_SMEM>>>(q_h, q_l, kv_h, kv_l, kv_h + 512, kv_l + 512,
                                       o_h, o_l, SS, SS, 512, 1024);
    gemm_mma<<<g512, 256, GEMM_SMEM>>>(o_h, o_l, w2o_h, w2o_l, a2bo, x1, x1, nullptr, nullptr, ROWS, 512, 512, 0);

    // --- fused GEGLU feed-forward ---
    ln_kernel<<<ROWS, 128>>>(x1, ln3g, ln3b, h_h, h_l);
    gemm_mma<<<gFF1, 256, GEMM_SMEM>>>(h_h, h_l, f1_h, f1_l, ffb1, nullptr, nullptr, a_h, a_l, ROWS, 4096, 512, 1);
    gemm_mma<<<g512, 256, GEMM_SMEM>>>(a_h, a_l, f2_h, f2_l, ffb2, x1, out, nullptr, nullptr, ROWS, 512, FFD, 0);
}